// round 1
// baseline (speedup 1.0000x reference)
#include <cuda_runtime.h>
#include <math.h>

// Problem shape (fixed by setup_inputs)
#define Bq 4
#define Sq 2048
#define Dq 1024
#define Fq 4096
#define Mq (Bq*Sq)   // 8192 rows

// ---------------- scratch (device globals; no runtime allocation) -------------
__device__ float g_xn [(size_t)Mq*Dq];   // layernormed activations (reused ln1/ln2)
__device__ float g_r  [(size_t)Mq*Dq];   // sigmoid(xn Wr^T)
__device__ float g_w  [(size_t)Mq*Dq];   // xn Ww^T (raw)
__device__ float g_k  [(size_t)Mq*Dq];   // xn Wk^T (raw)
__device__ float g_v  [(size_t)Mq*Dq];   // xn Wv^T
__device__ float g_wkv[(size_t)Mq*Dq];   // wkv from scan
__device__ float g_x1 [(size_t)Mq*Dq];   // x + time_mix
__device__ float g_r2 [(size_t)Mq*Dq];   // sigmoid(xn2 Wrec^T)
__device__ float g_k2 [(size_t)Mq*Fq];   // relu(xn2 Wkey^T)^2

// ---------------- layernorm: one block per row of D=1024 ----------------------
__global__ void ln_kernel(const float* __restrict__ x,
                          const float* __restrict__ gamma,
                          const float* __restrict__ beta,
                          float* __restrict__ out)
{
    const int row = blockIdx.x;
    const float4* xr = reinterpret_cast<const float4*>(x) + (size_t)row * (Dq/4);
    float4 v = xr[threadIdx.x];
    float s  = v.x + v.y + v.z + v.w;
    float ss = v.x*v.x + v.y*v.y + v.z*v.z + v.w*v.w;
    #pragma unroll
    for (int o = 16; o > 0; o >>= 1) {
        s  += __shfl_xor_sync(0xffffffffu, s,  o);
        ss += __shfl_xor_sync(0xffffffffu, ss, o);
    }
    __shared__ float rs[8], rss[8];
    const int warp = threadIdx.x >> 5;
    if ((threadIdx.x & 31) == 0) { rs[warp] = s; rss[warp] = ss; }
    __syncthreads();
    float ts = 0.f, tss = 0.f;
    #pragma unroll
    for (int i = 0; i < 8; i++) { ts += rs[i]; tss += rss[i]; }
    const float mu   = ts * (1.0f/Dq);
    const float var  = tss * (1.0f/Dq) - mu*mu;
    const float rstd = rsqrtf(var + 1e-5f);
    const float4 g4 = reinterpret_cast<const float4*>(gamma)[threadIdx.x];
    const float4 b4 = reinterpret_cast<const float4*>(beta )[threadIdx.x];
    float4 o;
    o.x = (v.x - mu)*rstd*g4.x + b4.x;
    o.y = (v.y - mu)*rstd*g4.y + b4.y;
    o.z = (v.z - mu)*rstd*g4.z + b4.z;
    o.w = (v.w - mu)*rstd*g4.w + b4.w;
    reinterpret_cast<float4*>(out)[(size_t)row*(Dq/4) + threadIdx.x] = o;
}

// ---------------- GEMM: C[M,N] = f( A[M,K] (*A2) @ W[N,K]^T ) ------------------
// EPI: 0 raw, 1 sigmoid, 2 relu^2, 3 acc + R, 4 R + MUL*acc
template<int EPI, bool HAS_A2>
__global__ void __launch_bounds__(256)
gemm_kernel(const float* __restrict__ A, const float* __restrict__ A2,
            const float* __restrict__ W, float* __restrict__ C,
            const float* __restrict__ R, const float* __restrict__ MUL,
            int M, int N, int K)
{
    constexpr int BM = 128, BN = 128, BK = 8;
    __shared__ float As[BK][BM];
    __shared__ float Bs[BK][BN];

    const int block_row = blockIdx.y * BM;
    const int block_col = blockIdx.x * BN;
    const int tid = threadIdx.x;
    const int lrow  = tid >> 1;            // 0..127 (row of the tile being loaded)
    const int lcol4 = (tid & 1) * 4;       // 0 or 4 within BK

    const float* Aptr  = A + (size_t)(block_row + lrow) * K + lcol4;
    const float* A2ptr = HAS_A2 ? (A2 + (size_t)(block_row + lrow) * K + lcol4) : nullptr;
    const float* Wptr  = W + (size_t)(block_col + lrow) * K + lcol4;

    const int ty = tid >> 4;   // 0..15
    const int tx = tid & 15;   // 0..15

    float acc[8][8];
    #pragma unroll
    for (int i = 0; i < 8; i++)
        #pragma unroll
        for (int j = 0; j < 8; j++) acc[i][j] = 0.f;

    for (int k0 = 0; k0 < K; k0 += BK) {
        float4 av = *reinterpret_cast<const float4*>(Aptr + k0);
        if (HAS_A2) {
            float4 a2 = *reinterpret_cast<const float4*>(A2ptr + k0);
            av.x *= a2.x; av.y *= a2.y; av.z *= a2.z; av.w *= a2.w;
        }
        const float4 bv = *reinterpret_cast<const float4*>(Wptr + k0);
        As[lcol4+0][lrow] = av.x; As[lcol4+1][lrow] = av.y;
        As[lcol4+2][lrow] = av.z; As[lcol4+3][lrow] = av.w;
        Bs[lcol4+0][lrow] = bv.x; Bs[lcol4+1][lrow] = bv.y;
        Bs[lcol4+2][lrow] = bv.z; Bs[lcol4+3][lrow] = bv.w;
        __syncthreads();

        #pragma unroll
        for (int kk = 0; kk < BK; kk++) {
            float ra[8], rb[8];
            #pragma unroll
            for (int i = 0; i < 8; i++) ra[i] = As[kk][ty*8 + i];
            #pragma unroll
            for (int j = 0; j < 8; j++) rb[j] = Bs[kk][tx*8 + j];
            #pragma unroll
            for (int i = 0; i < 8; i++)
                #pragma unroll
                for (int j = 0; j < 8; j++)
                    acc[i][j] = fmaf(ra[i], rb[j], acc[i][j]);
        }
        __syncthreads();
    }

    #pragma unroll
    for (int i = 0; i < 8; i++) {
        const size_t row  = (size_t)block_row + ty*8 + i;
        const size_t base = row * (size_t)N + block_col + tx*8;
        #pragma unroll
        for (int j = 0; j < 8; j += 4) {
            const float a0 = acc[i][j+0], a1 = acc[i][j+1];
            const float a2 = acc[i][j+2], a3 = acc[i][j+3];
            float4 o;
            if constexpr (EPI == 0) {
                o.x = a0; o.y = a1; o.z = a2; o.w = a3;
            } else if constexpr (EPI == 1) {
                o.x = 1.f/(1.f + expf(-a0)); o.y = 1.f/(1.f + expf(-a1));
                o.z = 1.f/(1.f + expf(-a2)); o.w = 1.f/(1.f + expf(-a3));
            } else if constexpr (EPI == 2) {
                float t0 = fmaxf(a0, 0.f), t1 = fmaxf(a1, 0.f);
                float t2 = fmaxf(a2, 0.f), t3 = fmaxf(a3, 0.f);
                o.x = t0*t0; o.y = t1*t1; o.z = t2*t2; o.w = t3*t3;
            } else if constexpr (EPI == 3) {
                const float4 rr = *reinterpret_cast<const float4*>(R + base + j);
                o.x = a0 + rr.x; o.y = a1 + rr.y; o.z = a2 + rr.z; o.w = a3 + rr.w;
            } else { // EPI == 4
                const float4 rr = *reinterpret_cast<const float4*>(R   + base + j);
                const float4 mm = *reinterpret_cast<const float4*>(MUL + base + j);
                o.x = rr.x + mm.x*a0; o.y = rr.y + mm.y*a1;
                o.z = rr.z + mm.z*a2; o.w = rr.w + mm.w*a3;
            }
            *reinterpret_cast<float4*>(C + base + j) = o;
        }
    }
}

// ---------------- WKV scan: one thread per (b,d) channel -----------------------
// Fuses ewk = exp(k - exp(w)) on the fly; writes final (num,den) to state[B,2,D].
__global__ void scan_kernel(const float* __restrict__ kk, const float* __restrict__ ww,
                            const float* __restrict__ vv, const float* __restrict__ td,
                            float* __restrict__ wkv, float* __restrict__ state,
                            int write_state)
{
    const int idx = blockIdx.x * blockDim.x + threadIdx.x;  // 0..4095
    const int b = idx >> 10;
    const int d = idx & (Dq - 1);
    const float decay = expf(td[d]);
    float num = 0.f, den = 0.f;
    const size_t base = (size_t)b * Sq * Dq + d;
    #pragma unroll 4
    for (int s = 0; s < Sq; s++) {
        const size_t off = base + (size_t)s * Dq;
        const float e = expf(kk[off] - expf(ww[off]));
        num = fmaf(decay, num, e * vv[off]);
        den = fmaf(decay, den, e);
        wkv[off] = num / (den + 1e-8f);
    }
    if (write_state) {
        state[(size_t)b*2*Dq + d]      = num;
        state[(size_t)b*2*Dq + Dq + d] = den;
    }
}

// ---------------- launch --------------------------------------------------------
extern "C" void kernel_launch(void* const* d_in, const int* in_sizes, int n_in,
                              void* d_out, int out_size)
{
    (void)in_sizes; (void)n_in;
    const float* x     = (const float*)d_in[0];
    const float* ln1_g = (const float*)d_in[1];
    const float* ln1_b = (const float*)d_in[2];
    const float* ln2_g = (const float*)d_in[3];
    const float* ln2_b = (const float*)d_in[4];
    const float* Wr    = (const float*)d_in[5];
    const float* Ww    = (const float*)d_in[6];
    const float* Wk    = (const float*)d_in[7];
    const float* Wv    = (const float*)d_in[8];
    const float* Wo    = (const float*)d_in[9];
    const float* td    = (const float*)d_in[10];
    // d_in[11] = time_first (unused by the reference)
    const float* Wkey  = (const float*)d_in[12];
    const float* Wval  = (const float*)d_in[13];
    const float* Wrec  = (const float*)d_in[14];

    float *xn, *r, *w, *k, *v, *wkv, *x1, *r2, *k2;
    cudaGetSymbolAddress((void**)&xn,  g_xn);
    cudaGetSymbolAddress((void**)&r,   g_r);
    cudaGetSymbolAddress((void**)&w,   g_w);
    cudaGetSymbolAddress((void**)&k,   g_k);
    cudaGetSymbolAddress((void**)&v,   g_v);
    cudaGetSymbolAddress((void**)&wkv, g_wkv);
    cudaGetSymbolAddress((void**)&x1,  g_x1);
    cudaGetSymbolAddress((void**)&r2,  g_r2);
    cudaGetSymbolAddress((void**)&k2,  g_k2);

    float* xout = (float*)d_out;
    const int write_state = (out_size >= Mq*Dq + Bq*2*Dq) ? 1 : 0;
    float* state = xout + (size_t)Mq*Dq;

    const dim3 gD(Dq/128, Mq/128);   // (8, 64)
    const dim3 gF(Fq/128, Mq/128);   // (32, 64)

    // ---- time mix ----
    ln_kernel<<<Mq, 256>>>(x, ln1_g, ln1_b, xn);
    gemm_kernel<1, false><<<gD, 256>>>(xn, nullptr, Wr, r,  nullptr, nullptr, Mq, Dq, Dq);
    gemm_kernel<0, false><<<gD, 256>>>(xn, nullptr, Ww, w,  nullptr, nullptr, Mq, Dq, Dq);
    gemm_kernel<0, false><<<gD, 256>>>(xn, nullptr, Wk, k,  nullptr, nullptr, Mq, Dq, Dq);
    gemm_kernel<0, false><<<gD, 256>>>(xn, nullptr, Wv, v,  nullptr, nullptr, Mq, Dq, Dq);
    scan_kernel<<<(Bq*Dq)/256, 256>>>(k, w, v, td, wkv, state, write_state);
    // x1 = x + (r*wkv) @ Wo^T
    gemm_kernel<3, true ><<<gD, 256>>>(r, wkv, Wo, x1, x, nullptr, Mq, Dq, Dq);

    // ---- channel mix ----
    ln_kernel<<<Mq, 256>>>(x1, ln2_g, ln2_b, xn);
    gemm_kernel<1, false><<<gD, 256>>>(xn, nullptr, Wrec, r2, nullptr, nullptr, Mq, Dq, Dq);
    gemm_kernel<2, false><<<gF, 256>>>(xn, nullptr, Wkey, k2, nullptr, nullptr, Mq, Fq, Dq);
    // out = x1 + r2 * (k2 @ Wval^T)
    gemm_kernel<4, false><<<gD, 256>>>(k2, nullptr, Wval, xout, x1, r2, Mq, Dq, Fq);
}

// round 3
// speedup vs baseline: 2.2109x; 2.2109x over previous
#include <cuda_runtime.h>
#include <cuda_bf16.h>
#include <cstdint>
#include <math.h>

#define Bq 4
#define Sq 2048
#define Dq 1024
#define Fq 4096
#define Mq (Bq*Sq)     // 8192
#define CH 16          // scan chunks
#define CL (Sq/CH)     // 128

// ---------------- scratch (device globals) ----------------
__device__ __nv_bfloat16 g_xnh[(size_t)Mq*Dq], g_xnl[(size_t)Mq*Dq];
__device__ __nv_bfloat16 g_wrh[(size_t)Dq*Dq], g_wrl[(size_t)Dq*Dq];
__device__ __nv_bfloat16 g_wwh[(size_t)Dq*Dq], g_wwl[(size_t)Dq*Dq];
__device__ __nv_bfloat16 g_wkh[(size_t)Dq*Dq], g_wkl[(size_t)Dq*Dq];
__device__ __nv_bfloat16 g_wvh[(size_t)Dq*Dq], g_wvl[(size_t)Dq*Dq];
__device__ __nv_bfloat16 g_woh[(size_t)Dq*Dq], g_wol[(size_t)Dq*Dq];
__device__ __nv_bfloat16 g_wrech[(size_t)Dq*Dq], g_wrecl[(size_t)Dq*Dq];
__device__ __nv_bfloat16 g_wkeyh[(size_t)Fq*Dq], g_wkeyl[(size_t)Fq*Dq];
__device__ __nv_bfloat16 g_wvalh[(size_t)Dq*Fq], g_wvall[(size_t)Dq*Fq];
__device__ float g_r  [(size_t)Mq*Dq];
__device__ float g_w  [(size_t)Mq*Dq];
__device__ float g_k  [(size_t)Mq*Dq];
__device__ float g_v  [(size_t)Mq*Dq];
__device__ float g_wkv[(size_t)Mq*Dq];
__device__ float g_x1 [(size_t)Mq*Dq];
__device__ float g_r2 [(size_t)Mq*Dq];
__device__ __nv_bfloat16 g_rwh[(size_t)Mq*Dq], g_rwl[(size_t)Mq*Dq];
__device__ __nv_bfloat16 g_k2h[(size_t)Mq*Fq], g_k2l[(size_t)Mq*Fq];
__device__ float g_loc [(size_t)CH*Bq*2*Dq];   // per-chunk local (num,den)
__device__ float g_strt[(size_t)CH*Bq*2*Dq];   // per-chunk start carries

// ---------------- helpers ----------------
__device__ __forceinline__ uint32_t packbf(__nv_bfloat16 a, __nv_bfloat16 b) {
    __nv_bfloat162 p(a, b);
    return *reinterpret_cast<uint32_t*>(&p);
}
__device__ __forceinline__ void split4(float4 v, uint2& h, uint2& l) {
    __nv_bfloat16 h0 = __float2bfloat16(v.x), h1 = __float2bfloat16(v.y);
    __nv_bfloat16 h2 = __float2bfloat16(v.z), h3 = __float2bfloat16(v.w);
    __nv_bfloat16 l0 = __float2bfloat16(v.x - __bfloat162float(h0));
    __nv_bfloat16 l1 = __float2bfloat16(v.y - __bfloat162float(h1));
    __nv_bfloat16 l2 = __float2bfloat16(v.z - __bfloat162float(h2));
    __nv_bfloat16 l3 = __float2bfloat16(v.w - __bfloat162float(h3));
    h.x = packbf(h0,h1); h.y = packbf(h2,h3);
    l.x = packbf(l0,l1); l.y = packbf(l2,l3);
}

// ---------------- f32 -> bf16 hi/lo split ----------------
__global__ void split_kernel(const float4* __restrict__ src,
                             uint2* __restrict__ hi, uint2* __restrict__ lo, int n4)
{
    int i = blockIdx.x * blockDim.x + threadIdx.x;
    if (i >= n4) return;
    uint2 h, l; split4(src[i], h, l);
    hi[i] = h; lo[i] = l;
}

// ---------------- layernorm + split ----------------
__global__ void ln_split_kernel(const float* __restrict__ x,
                                const float* __restrict__ gamma,
                                const float* __restrict__ beta,
                                uint2* __restrict__ oh, uint2* __restrict__ ol)
{
    const int row = blockIdx.x;
    const float4* xr = reinterpret_cast<const float4*>(x) + (size_t)row * (Dq/4);
    float4 v = xr[threadIdx.x];
    float s  = v.x + v.y + v.z + v.w;
    float ss = v.x*v.x + v.y*v.y + v.z*v.z + v.w*v.w;
    #pragma unroll
    for (int o = 16; o > 0; o >>= 1) {
        s  += __shfl_xor_sync(0xffffffffu, s,  o);
        ss += __shfl_xor_sync(0xffffffffu, ss, o);
    }
    __shared__ float rs[8], rss[8];
    const int warp = threadIdx.x >> 5;
    if ((threadIdx.x & 31) == 0) { rs[warp] = s; rss[warp] = ss; }
    __syncthreads();
    float ts = 0.f, tss = 0.f;
    #pragma unroll
    for (int i = 0; i < 8; i++) { ts += rs[i]; tss += rss[i]; }
    const float mu   = ts * (1.0f/Dq);
    const float var  = tss * (1.0f/Dq) - mu*mu;
    const float rstd = rsqrtf(var + 1e-5f);
    const float4 g4 = reinterpret_cast<const float4*>(gamma)[threadIdx.x];
    const float4 b4 = reinterpret_cast<const float4*>(beta )[threadIdx.x];
    float4 o;
    o.x = (v.x - mu)*rstd*g4.x + b4.x;
    o.y = (v.y - mu)*rstd*g4.y + b4.y;
    o.z = (v.z - mu)*rstd*g4.z + b4.z;
    o.w = (v.w - mu)*rstd*g4.w + b4.w;
    uint2 h, l; split4(o, h, l);
    const size_t idx = (size_t)row * (Dq/4) + threadIdx.x;
    oh[idx] = h; ol[idx] = l;
}

// ---------------- r*wkv product + split ----------------
__global__ void mulsplit_kernel(const float4* __restrict__ a, const float4* __restrict__ b,
                                uint2* __restrict__ hi, uint2* __restrict__ lo, int n4)
{
    int i = blockIdx.x * blockDim.x + threadIdx.x;
    if (i >= n4) return;
    float4 x = a[i], y = b[i];
    float4 p = make_float4(x.x*y.x, x.y*y.y, x.z*y.z, x.w*y.w);
    uint2 h, l; split4(p, h, l);
    hi[i] = h; lo[i] = l;
}

// ---------------- tensor-core GEMM (3x bf16 split) ----------------
// C[M,N] = f( A[M,K] @ W[N,K]^T ),  A ~ Ah+Al, W ~ Bh+Bl (bf16), fp32 accum
// EPI: 0 raw, 1 sigmoid, 2 relu^2 -> bf16 hi/lo, 3 acc+R, 4 R + MUL*acc
#define LDT 24   // BK(16)+8 halves
template<int EPI>
__global__ void __launch_bounds__(256)
mma_gemm(const __nv_bfloat16* __restrict__ Ah, const __nv_bfloat16* __restrict__ Al,
         const __nv_bfloat16* __restrict__ Bh, const __nv_bfloat16* __restrict__ Bl,
         float* __restrict__ C, __nv_bfloat16* __restrict__ Ch, __nv_bfloat16* __restrict__ Cl,
         const float* __restrict__ R, const float* __restrict__ MUL,
         int M, int N, int K)
{
    __shared__ __align__(16) __nv_bfloat16 sAh[128*LDT], sAl[128*LDT];
    __shared__ __align__(16) __nv_bfloat16 sBh[128*LDT], sBl[128*LDT];

    const int tid = threadIdx.x;
    const int block_row = blockIdx.y * 128;
    const int block_col = blockIdx.x * 128;

    // gmem tile loaders: thread -> (row = tid>>1, 8 halves at (tid&1)*8)
    const int lrow = tid >> 1;
    const int lc8  = (tid & 1) * 8;
    const __nv_bfloat16* gAh = Ah + (size_t)(block_row + lrow) * K + lc8;
    const __nv_bfloat16* gAl = Al + (size_t)(block_row + lrow) * K + lc8;
    const __nv_bfloat16* gBh = Bh + (size_t)(block_col + lrow) * K + lc8;
    const __nv_bfloat16* gBl = Bl + (size_t)(block_col + lrow) * K + lc8;
    const int ssto = lrow * LDT + lc8;

    const int lane = tid & 31;
    const int wm = (tid >> 7);        // 0..1
    const int wn = (tid >> 5) & 3;    // 0..3
    const int grp = lane >> 2, qid = lane & 3;
    const int mb = wm * 64, nb = wn * 32;

    float acc[4][4][4];
    #pragma unroll
    for (int i = 0; i < 4; i++)
        #pragma unroll
        for (int j = 0; j < 4; j++)
            #pragma unroll
            for (int q = 0; q < 4; q++) acc[i][j][q] = 0.f;

    uint4 pAh, pAl, pBh, pBl;
    pAh = *reinterpret_cast<const uint4*>(gAh);
    pAl = *reinterpret_cast<const uint4*>(gAl);
    pBh = *reinterpret_cast<const uint4*>(gBh);
    pBl = *reinterpret_cast<const uint4*>(gBl);

    const int KT = K >> 4;
    for (int kt = 0; kt < KT; kt++) {
        *reinterpret_cast<uint4*>(&sAh[ssto]) = pAh;
        *reinterpret_cast<uint4*>(&sAl[ssto]) = pAl;
        *reinterpret_cast<uint4*>(&sBh[ssto]) = pBh;
        *reinterpret_cast<uint4*>(&sBl[ssto]) = pBl;
        __syncthreads();
        if (kt + 1 < KT) {
            const int ko = (kt + 1) << 4;
            pAh = *reinterpret_cast<const uint4*>(gAh + ko);
            pAl = *reinterpret_cast<const uint4*>(gAl + ko);
            pBh = *reinterpret_cast<const uint4*>(gBh + ko);
            pBl = *reinterpret_cast<const uint4*>(gBl + ko);
        }

        uint32_t ah[4][4], al[4][4], bh[4][2], bl[4][2];
        const int c0 = 2*qid, c1 = 2*qid + 8;
        #pragma unroll
        for (int mt = 0; mt < 4; mt++) {
            const int r0 = (mb + mt*16 + grp) * LDT;
            const int r1 = r0 + 8*LDT;
            ah[mt][0] = *reinterpret_cast<const uint32_t*>(&sAh[r0 + c0]);
            ah[mt][1] = *reinterpret_cast<const uint32_t*>(&sAh[r1 + c0]);
            ah[mt][2] = *reinterpret_cast<const uint32_t*>(&sAh[r0 + c1]);
            ah[mt][3] = *reinterpret_cast<const uint32_t*>(&sAh[r1 + c1]);
            al[mt][0] = *reinterpret_cast<const uint32_t*>(&sAl[r0 + c0]);
            al[mt][1] = *reinterpret_cast<const uint32_t*>(&sAl[r1 + c0]);
            al[mt][2] = *reinterpret_cast<const uint32_t*>(&sAl[r0 + c1]);
            al[mt][3] = *reinterpret_cast<const uint32_t*>(&sAl[r1 + c1]);
        }
        #pragma unroll
        for (int nt = 0; nt < 4; nt++) {
            const int n0 = (nb + nt*8 + grp) * LDT;
            bh[nt][0] = *reinterpret_cast<const uint32_t*>(&sBh[n0 + c0]);
            bh[nt][1] = *reinterpret_cast<const uint32_t*>(&sBh[n0 + c1]);
            bl[nt][0] = *reinterpret_cast<const uint32_t*>(&sBl[n0 + c0]);
            bl[nt][1] = *reinterpret_cast<const uint32_t*>(&sBl[n0 + c1]);
        }

        #pragma unroll
        for (int mt = 0; mt < 4; mt++)
            #pragma unroll
            for (int nt = 0; nt < 4; nt++) {
                float* c = acc[mt][nt];
                asm volatile(
                    "mma.sync.aligned.m16n8k16.row.col.f32.bf16.bf16.f32 "
                    "{%0,%1,%2,%3}, {%4,%5,%6,%7}, {%8,%9}, {%0,%1,%2,%3};\n"
                    : "+f"(c[0]), "+f"(c[1]), "+f"(c[2]), "+f"(c[3])
                    : "r"(ah[mt][0]), "r"(ah[mt][1]), "r"(ah[mt][2]), "r"(ah[mt][3]),
                      "r"(bh[nt][0]), "r"(bh[nt][1]));
                asm volatile(
                    "mma.sync.aligned.m16n8k16.row.col.f32.bf16.bf16.f32 "
                    "{%0,%1,%2,%3}, {%4,%5,%6,%7}, {%8,%9}, {%0,%1,%2,%3};\n"
                    : "+f"(c[0]), "+f"(c[1]), "+f"(c[2]), "+f"(c[3])
                    : "r"(ah[mt][0]), "r"(ah[mt][1]), "r"(ah[mt][2]), "r"(ah[mt][3]),
                      "r"(bl[nt][0]), "r"(bl[nt][1]));
                asm volatile(
                    "mma.sync.aligned.m16n8k16.row.col.f32.bf16.bf16.f32 "
                    "{%0,%1,%2,%3}, {%4,%5,%6,%7}, {%8,%9}, {%0,%1,%2,%3};\n"
                    : "+f"(c[0]), "+f"(c[1]), "+f"(c[2]), "+f"(c[3])
                    : "r"(al[mt][0]), "r"(al[mt][1]), "r"(al[mt][2]), "r"(al[mt][3]),
                      "r"(bh[nt][0]), "r"(bh[nt][1]));
            }
        __syncthreads();
    }

    // epilogue
    #pragma unroll
    for (int mt = 0; mt < 4; mt++) {
        const size_t r0 = (size_t)block_row + mb + mt*16 + grp;
        const size_t r1 = r0 + 8;
        #pragma unroll
        for (int nt = 0; nt < 4; nt++) {
            const int col = block_col + nb + nt*8 + 2*qid;
            const float* c = acc[mt][nt];
            const size_t i0 = r0 * (size_t)N + col;
            const size_t i1 = r1 * (size_t)N + col;
            if constexpr (EPI == 2) {
                float t0 = fmaxf(c[0],0.f), t1 = fmaxf(c[1],0.f);
                float t2 = fmaxf(c[2],0.f), t3 = fmaxf(c[3],0.f);
                float q0 = t0*t0, q1 = t1*t1, q2 = t2*t2, q3 = t3*t3;
                __nv_bfloat16 h0=__float2bfloat16(q0), h1=__float2bfloat16(q1);
                __nv_bfloat16 h2=__float2bfloat16(q2), h3=__float2bfloat16(q3);
                __nv_bfloat16 l0=__float2bfloat16(q0-__bfloat162float(h0));
                __nv_bfloat16 l1=__float2bfloat16(q1-__bfloat162float(h1));
                __nv_bfloat16 l2=__float2bfloat16(q2-__bfloat162float(h2));
                __nv_bfloat16 l3=__float2bfloat16(q3-__bfloat162float(h3));
                *reinterpret_cast<uint32_t*>(&Ch[i0]) = packbf(h0,h1);
                *reinterpret_cast<uint32_t*>(&Ch[i1]) = packbf(h2,h3);
                *reinterpret_cast<uint32_t*>(&Cl[i0]) = packbf(l0,l1);
                *reinterpret_cast<uint32_t*>(&Cl[i1]) = packbf(l2,l3);
            } else {
                float2 o0, o1;
                if constexpr (EPI == 0) {
                    o0 = make_float2(c[0], c[1]); o1 = make_float2(c[2], c[3]);
                } else if constexpr (EPI == 1) {
                    o0 = make_float2(1.f/(1.f+expf(-c[0])), 1.f/(1.f+expf(-c[1])));
                    o1 = make_float2(1.f/(1.f+expf(-c[2])), 1.f/(1.f+expf(-c[3])));
                } else if constexpr (EPI == 3) {
                    const float2 rr0 = *reinterpret_cast<const float2*>(R + i0);
                    const float2 rr1 = *reinterpret_cast<const float2*>(R + i1);
                    o0 = make_float2(c[0] + rr0.x, c[1] + rr0.y);
                    o1 = make_float2(c[2] + rr1.x, c[3] + rr1.y);
                } else { // EPI 4
                    const float2 rr0 = *reinterpret_cast<const float2*>(R + i0);
                    const float2 rr1 = *reinterpret_cast<const float2*>(R + i1);
                    const float2 mm0 = *reinterpret_cast<const float2*>(MUL + i0);
                    const float2 mm1 = *reinterpret_cast<const float2*>(MUL + i1);
                    o0 = make_float2(rr0.x + mm0.x*c[0], rr0.y + mm0.y*c[1]);
                    o1 = make_float2(rr1.x + mm1.x*c[2], rr1.y + mm1.y*c[3]);
                }
                *reinterpret_cast<float2*>(C + i0) = o0;
                *reinterpret_cast<float2*>(C + i1) = o1;
            }
        }
    }
}

// ---------------- chunked WKV scan ----------------
// phase1: per-(chunk,b,d) local scan -> (num,den) local results
__global__ void scan_p1(const float* __restrict__ kk, const float* __restrict__ ww,
                        const float* __restrict__ vv, const float* __restrict__ td,
                        float* __restrict__ loc)
{
    const int idx = blockIdx.x * blockDim.x + threadIdx.x;  // CH*B*D
    const int c  = idx >> 12;
    const int bd = idx & 4095;
    const int b  = bd >> 10;
    const int d  = bd & 1023;
    const float decay = expf(td[d]);
    float num = 0.f, den = 0.f;
    const size_t base = (size_t)b * Sq * Dq + (size_t)c * CL * Dq + d;
    #pragma unroll 4
    for (int s = 0; s < CL; s++) {
        const size_t off = base + (size_t)s * Dq;
        const float e = expf(kk[off] - expf(ww[off]));
        num = fmaf(decay, num, e * vv[off]);
        den = fmaf(decay, den, e);
    }
    const size_t ci = ((size_t)c * Bq + b) * 2 * Dq + d;
    loc[ci]      = num;
    loc[ci + Dq] = den;
}

// phase2: sequential combine over chunks; emits per-chunk start carries + final state
__global__ void scan_p2(const float* __restrict__ loc, const float* __restrict__ td,
                        float* __restrict__ strt, float* __restrict__ state, int write_state)
{
    const int idx = blockIdx.x * blockDim.x + threadIdx.x;  // B*D
    const int b = idx >> 10;
    const int d = idx & 1023;
    const float dl = expf(td[d] * (float)CL);   // decay^CL
    float cn = 0.f, cd = 0.f;
    for (int c = 0; c < CH; c++) {
        const size_t ci = ((size_t)c * Bq + b) * 2 * Dq + d;
        strt[ci]      = cn;
        strt[ci + Dq] = cd;
        cn = dl * cn + loc[ci];
        cd = dl * cd + loc[ci + Dq];
    }
    if (write_state) {
        state[(size_t)b*2*Dq + d]      = cn;
        state[(size_t)b*2*Dq + Dq + d] = cd;
    }
}

// phase3: re-scan with start carries, write wkv
__global__ void scan_p3(const float* __restrict__ kk, const float* __restrict__ ww,
                        const float* __restrict__ vv, const float* __restrict__ td,
                        const float* __restrict__ strt, float* __restrict__ wkv)
{
    const int idx = blockIdx.x * blockDim.x + threadIdx.x;
    const int c  = idx >> 12;
    const int bd = idx & 4095;
    const int b  = bd >> 10;
    const int d  = bd & 1023;
    const float decay = expf(td[d]);
    const size_t ci = ((size_t)c * Bq + b) * 2 * Dq + d;
    float num = strt[ci], den = strt[ci + Dq];
    const size_t base = (size_t)b * Sq * Dq + (size_t)c * CL * Dq + d;
    #pragma unroll 4
    for (int s = 0; s < CL; s++) {
        const size_t off = base + (size_t)s * Dq;
        const float e = expf(kk[off] - expf(ww[off]));
        num = fmaf(decay, num, e * vv[off]);
        den = fmaf(decay, den, e);
        wkv[off] = num / (den + 1e-8f);
    }
}

// ---------------- launch ----------------
extern "C" void kernel_launch(void* const* d_in, const int* in_sizes, int n_in,
                              void* d_out, int out_size)
{
    (void)in_sizes; (void)n_in;
    const float* x     = (const float*)d_in[0];
    const float* ln1_g = (const float*)d_in[1];
    const float* ln1_b = (const float*)d_in[2];
    const float* ln2_g = (const float*)d_in[3];
    const float* ln2_b = (const float*)d_in[4];
    const float* Wr    = (const float*)d_in[5];
    const float* Ww    = (const float*)d_in[6];
    const float* Wk    = (const float*)d_in[7];
    const float* Wv    = (const float*)d_in[8];
    const float* Wo    = (const float*)d_in[9];
    const float* td    = (const float*)d_in[10];
    const float* Wkey  = (const float*)d_in[12];
    const float* Wval  = (const float*)d_in[13];
    const float* Wrec  = (const float*)d_in[14];

    __nv_bfloat16 *xnh,*xnl,*wrh,*wrl,*wwh,*wwl,*wkh,*wkl,*wvh,*wvl,*woh,*wol;
    __nv_bfloat16 *wrech,*wrecl,*wkeyh,*wkeyl,*wvalh,*wvall,*rwh,*rwl,*k2h,*k2l;
    float *r,*w,*k,*v,*wkv,*x1,*r2,*loc,*strt;
    cudaGetSymbolAddress((void**)&xnh, g_xnh);   cudaGetSymbolAddress((void**)&xnl, g_xnl);
    cudaGetSymbolAddress((void**)&wrh, g_wrh);   cudaGetSymbolAddress((void**)&wrl, g_wrl);
    cudaGetSymbolAddress((void**)&wwh, g_wwh);   cudaGetSymbolAddress((void**)&wwl, g_wwl);
    cudaGetSymbolAddress((void**)&wkh, g_wkh);   cudaGetSymbolAddress((void**)&wkl, g_wkl);
    cudaGetSymbolAddress((void**)&wvh, g_wvh);   cudaGetSymbolAddress((void**)&wvl, g_wvl);
    cudaGetSymbolAddress((void**)&woh, g_woh);   cudaGetSymbolAddress((void**)&wol, g_wol);
    cudaGetSymbolAddress((void**)&wrech, g_wrech); cudaGetSymbolAddress((void**)&wrecl, g_wrecl);
    cudaGetSymbolAddress((void**)&wkeyh, g_wkeyh); cudaGetSymbolAddress((void**)&wkeyl, g_wkeyl);
    cudaGetSymbolAddress((void**)&wvalh, g_wvalh); cudaGetSymbolAddress((void**)&wvall, g_wvall);
    cudaGetSymbolAddress((void**)&rwh, g_rwh);   cudaGetSymbolAddress((void**)&rwl, g_rwl);
    cudaGetSymbolAddress((void**)&k2h, g_k2h);   cudaGetSymbolAddress((void**)&k2l, g_k2l);
    cudaGetSymbolAddress((void**)&r, g_r);       cudaGetSymbolAddress((void**)&w, g_w);
    cudaGetSymbolAddress((void**)&k, g_k);       cudaGetSymbolAddress((void**)&v, g_v);
    cudaGetSymbolAddress((void**)&wkv, g_wkv);   cudaGetSymbolAddress((void**)&x1, g_x1);
    cudaGetSymbolAddress((void**)&r2, g_r2);
    cudaGetSymbolAddress((void**)&loc, g_loc);   cudaGetSymbolAddress((void**)&strt, g_strt);

    float* xout = (float*)d_out;
    const int write_state = (out_size >= Mq*Dq + Bq*2*Dq) ? 1 : 0;
    float* state = xout + (size_t)Mq*Dq;

    const int nDD4 = Dq*Dq/4, nFD4 = Fq*Dq/4, nMD4 = Mq*Dq/4;

    // weight splits
    split_kernel<<<nDD4/256, 256>>>((const float4*)Wr,   (uint2*)wrh,   (uint2*)wrl,   nDD4);
    split_kernel<<<nDD4/256, 256>>>((const float4*)Ww,   (uint2*)wwh,   (uint2*)wwl,   nDD4);
    split_kernel<<<nDD4/256, 256>>>((const float4*)Wk,   (uint2*)wkh,   (uint2*)wkl,   nDD4);
    split_kernel<<<nDD4/256, 256>>>((const float4*)Wv,   (uint2*)wvh,   (uint2*)wvl,   nDD4);
    split_kernel<<<nDD4/256, 256>>>((const float4*)Wo,   (uint2*)woh,   (uint2*)wol,   nDD4);
    split_kernel<<<nDD4/256, 256>>>((const float4*)Wrec, (uint2*)wrech, (uint2*)wrecl, nDD4);
    split_kernel<<<nFD4/256, 256>>>((const float4*)Wkey, (uint2*)wkeyh, (uint2*)wkeyl, nFD4);
    split_kernel<<<nFD4/256, 256>>>((const float4*)Wval, (uint2*)wvalh, (uint2*)wvall, nFD4);

    const dim3 gD(Dq/128, Mq/128);   // (8, 64)
    const dim3 gF(Fq/128, Mq/128);   // (32, 64)

    // ---- time mix ----
    ln_split_kernel<<<Mq, 256>>>(x, ln1_g, ln1_b, (uint2*)xnh, (uint2*)xnl);
    mma_gemm<1><<<gD, 256>>>(xnh, xnl, wrh, wrl, r, nullptr, nullptr, nullptr, nullptr, Mq, Dq, Dq);
    mma_gemm<0><<<gD, 256>>>(xnh, xnl, wwh, wwl, w, nullptr, nullptr, nullptr, nullptr, Mq, Dq, Dq);
    mma_gemm<0><<<gD, 256>>>(xnh, xnl, wkh, wkl, k, nullptr, nullptr, nullptr, nullptr, Mq, Dq, Dq);
    mma_gemm<0><<<gD, 256>>>(xnh, xnl, wvh, wvl, v, nullptr, nullptr, nullptr, nullptr, Mq, Dq, Dq);
    scan_p1<<<(CH*Bq*Dq)/256, 256>>>(k, w, v, td, loc);
    scan_p2<<<(Bq*Dq)/256, 256>>>(loc, td, strt, state, write_state);
    scan_p3<<<(CH*Bq*Dq)/256, 256>>>(k, w, v, td, strt, wkv);
    mulsplit_kernel<<<nMD4/256, 256>>>((const float4*)r, (const float4*)wkv, (uint2*)rwh, (uint2*)rwl, nMD4);
    mma_gemm<3><<<gD, 256>>>(rwh, rwl, woh, wol, x1, nullptr, nullptr, x, nullptr, Mq, Dq, Dq);

    // ---- channel mix ----
    ln_split_kernel<<<Mq, 256>>>(x1, ln2_g, ln2_b, (uint2*)xnh, (uint2*)xnl);
    mma_gemm<1><<<gD, 256>>>(xnh, xnl, wrech, wrecl, r2, nullptr, nullptr, nullptr, nullptr, Mq, Dq, Dq);
    mma_gemm<2><<<gF, 256>>>(xnh, xnl, wkeyh, wkeyl, nullptr, k2h, k2l, nullptr, nullptr, Mq, Fq, Dq);
    mma_gemm<4><<<gD, 256>>>(k2h, k2l, wvalh, wvall, xout, nullptr, nullptr, x1, r2, Mq, Dq, Fq);
}

// round 4
// speedup vs baseline: 2.8865x; 1.3055x over previous
#include <cuda_runtime.h>
#include <cuda_bf16.h>
#include <cstdint>
#include <math.h>

#define Bq 4
#define Sq 2048
#define Dq 1024
#define Fq 4096
#define Mq (Bq*Sq)     // 8192
#define CH 16
#define CL (Sq/CH)     // 128
#define LDT 40         // smem row stride in halves (BK=32 + 8 pad)
#define STAGE_H (128*LDT)          // halves per tile (5120)
#define SMEM_BYTES (2*4*STAGE_H*2) // 2 stages * 4 tiles * 5120 halves * 2B = 81920

// ---------------- scratch ----------------
__device__ __nv_bfloat16 g_xnh[(size_t)Mq*Dq], g_xnl[(size_t)Mq*Dq];
__device__ __nv_bfloat16 g_wqkvwh[(size_t)4*Dq*Dq], g_wqkvwl[(size_t)4*Dq*Dq]; // [r|w|k|v][D,D]
__device__ __nv_bfloat16 g_woh[(size_t)Dq*Dq], g_wol[(size_t)Dq*Dq];
__device__ __nv_bfloat16 g_wrkh[(size_t)(Dq+Fq)*Dq], g_wrkl[(size_t)(Dq+Fq)*Dq]; // [rec|key]
__device__ __nv_bfloat16 g_wvalh[(size_t)Dq*Fq], g_wvall[(size_t)Dq*Fq];
__device__ float g_act[(size_t)Mq*4*Dq];   // fused r|w|k|v outputs [M, 4096]
__device__ float g_x1 [(size_t)Mq*Dq];
__device__ float g_r2 [(size_t)Mq*Dq];
__device__ __nv_bfloat16 g_rwh[(size_t)Mq*Dq], g_rwl[(size_t)Mq*Dq];
__device__ __nv_bfloat16 g_k2h[(size_t)Mq*Fq], g_k2l[(size_t)Mq*Fq];
__device__ float g_loc[(size_t)CH*Bq*2*Dq];

// ---------------- helpers ----------------
__device__ __forceinline__ uint32_t packbf(__nv_bfloat16 a, __nv_bfloat16 b) {
    __nv_bfloat162 p(a, b);
    return *reinterpret_cast<uint32_t*>(&p);
}
__device__ __forceinline__ void split4(float4 v, uint2& h, uint2& l) {
    __nv_bfloat16 h0 = __float2bfloat16(v.x), h1 = __float2bfloat16(v.y);
    __nv_bfloat16 h2 = __float2bfloat16(v.z), h3 = __float2bfloat16(v.w);
    __nv_bfloat16 l0 = __float2bfloat16(v.x - __bfloat162float(h0));
    __nv_bfloat16 l1 = __float2bfloat16(v.y - __bfloat162float(h1));
    __nv_bfloat16 l2 = __float2bfloat16(v.z - __bfloat162float(h2));
    __nv_bfloat16 l3 = __float2bfloat16(v.w - __bfloat162float(h3));
    h.x = packbf(h0,h1); h.y = packbf(h2,h3);
    l.x = packbf(l0,l1); l.y = packbf(l2,l3);
}

// ---------------- fused weight split: one launch for all 8 matrices ----------------
struct SplitJob  { const float4* s; uint2* h; uint2* l; int n4; };
struct SplitJobs { SplitJob j[8]; };
__global__ void splitall_kernel(SplitJobs js)
{
    const SplitJob jb = js.j[blockIdx.y];
    const int i = blockIdx.x * blockDim.x + threadIdx.x;
    if (i >= jb.n4) return;
    uint2 h, l; split4(jb.s[i], h, l);
    jb.h[i] = h; jb.l[i] = l;
}

// ---------------- layernorm + split ----------------
__global__ void ln_split_kernel(const float* __restrict__ x,
                                const float* __restrict__ gamma,
                                const float* __restrict__ beta,
                                uint2* __restrict__ oh, uint2* __restrict__ ol)
{
    const int row = blockIdx.x;
    const float4* xr = reinterpret_cast<const float4*>(x) + (size_t)row * (Dq/4);
    float4 v = xr[threadIdx.x];
    float s  = v.x + v.y + v.z + v.w;
    float ss = v.x*v.x + v.y*v.y + v.z*v.z + v.w*v.w;
    #pragma unroll
    for (int o = 16; o > 0; o >>= 1) {
        s  += __shfl_xor_sync(0xffffffffu, s,  o);
        ss += __shfl_xor_sync(0xffffffffu, ss, o);
    }
    __shared__ float rs[8], rss[8];
    const int warp = threadIdx.x >> 5;
    if ((threadIdx.x & 31) == 0) { rs[warp] = s; rss[warp] = ss; }
    __syncthreads();
    float ts = 0.f, tss = 0.f;
    #pragma unroll
    for (int i = 0; i < 8; i++) { ts += rs[i]; tss += rss[i]; }
    const float mu   = ts * (1.0f/Dq);
    const float var  = tss * (1.0f/Dq) - mu*mu;
    const float rstd = rsqrtf(var + 1e-5f);
    const float4 g4 = reinterpret_cast<const float4*>(gamma)[threadIdx.x];
    const float4 b4 = reinterpret_cast<const float4*>(beta )[threadIdx.x];
    float4 o;
    o.x = (v.x - mu)*rstd*g4.x + b4.x;
    o.y = (v.y - mu)*rstd*g4.y + b4.y;
    o.z = (v.z - mu)*rstd*g4.z + b4.z;
    o.w = (v.w - mu)*rstd*g4.w + b4.w;
    uint2 h, l; split4(o, h, l);
    const size_t idx = (size_t)row * (Dq/4) + threadIdx.x;
    oh[idx] = h; ol[idx] = l;
}

// ---------------- tensor-core GEMM, cp.async 2-stage, BK=32 ----------------
// EPI: 3 = acc + R                     (Wo GEMM, N=1024)
//      4 = R + MUL*acc                 (Wval GEMM, N=1024)
//      5 = fused qkvw: col<1024 sigmoid else raw, float out [M,4096]
//      6 = fused rec|key: col<1024 sigmoid->C[M,1024]; else relu^2 -> Ch/Cl[M,4096]
template<int EPI>
__global__ void __launch_bounds__(256)
mma_gemm(const __nv_bfloat16* __restrict__ Ah, const __nv_bfloat16* __restrict__ Al,
         const __nv_bfloat16* __restrict__ Bh, const __nv_bfloat16* __restrict__ Bl,
         float* __restrict__ C, __nv_bfloat16* __restrict__ Ch, __nv_bfloat16* __restrict__ Cl,
         const float* __restrict__ R, const float* __restrict__ MUL,
         int N, int K)
{
    extern __shared__ __nv_bfloat16 dyn[];

    const int tid = threadIdx.x;
    const int block_row = blockIdx.y * 128;
    const int block_col = blockIdx.x * 128;

    const uint32_t sbase = (uint32_t)__cvta_generic_to_shared(dyn);

    // loader indices: 2 threads per row, each does 2 x 16B per tile
    const int lr = tid >> 1;
    const int sg = (tid & 1) * 2;
    const __nv_bfloat16* gA_h = Ah + (size_t)(block_row + lr) * K;
    const __nv_bfloat16* gA_l = Al + (size_t)(block_row + lr) * K;
    const __nv_bfloat16* gB_h = Bh + (size_t)(block_col + lr) * K;
    const __nv_bfloat16* gB_l = Bl + (size_t)(block_col + lr) * K;
    const uint32_t srow = sbase + (uint32_t)(lr * LDT) * 2;

    #define LOADSTAGE(st, ko)                                                          \
    do {                                                                               \
        const uint32_t sb = srow + (uint32_t)(st) * (4*STAGE_H*2);                     \
        _Pragma("unroll")                                                              \
        for (int j = 0; j < 2; j++) {                                                  \
            const int sj = sg + j;                                                     \
            const uint32_t co = (uint32_t)sj * 16;                                     \
            asm volatile("cp.async.cg.shared.global [%0], [%1], 16;" ::                \
                "r"(sb + 0*STAGE_H*2 + co), "l"(gA_h + (ko) + sj*8));                  \
            asm volatile("cp.async.cg.shared.global [%0], [%1], 16;" ::                \
                "r"(sb + 1*STAGE_H*2 + co), "l"(gA_l + (ko) + sj*8));                  \
            asm volatile("cp.async.cg.shared.global [%0], [%1], 16;" ::                \
                "r"(sb + 2*STAGE_H*2 + co), "l"(gB_h + (ko) + sj*8));                  \
            asm volatile("cp.async.cg.shared.global [%0], [%1], 16;" ::                \
                "r"(sb + 3*STAGE_H*2 + co), "l"(gB_l + (ko) + sj*8));                  \
        }                                                                              \
        asm volatile("cp.async.commit_group;");                                       \
    } while (0)

    const int lane = tid & 31;
    const int wm = (tid >> 7);
    const int wn = (tid >> 5) & 3;
    const int grp = lane >> 2, qid = lane & 3;
    const int mb = wm * 64, nb = wn * 32;

    float acc[4][4][4];
    #pragma unroll
    for (int i = 0; i < 4; i++)
        #pragma unroll
        for (int j = 0; j < 4; j++)
            #pragma unroll
            for (int q = 0; q < 4; q++) acc[i][j][q] = 0.f;

    const int KT = K >> 5;
    LOADSTAGE(0, 0);

    for (int kt = 0; kt < KT; kt++) {
        asm volatile("cp.async.wait_group 0;");
        __syncthreads();
        if (kt + 1 < KT) LOADSTAGE((kt + 1) & 1, (kt + 1) * 32);

        const __nv_bfloat16* sAh = dyn + (kt & 1) * (4*STAGE_H);
        const __nv_bfloat16* sAl = sAh + STAGE_H;
        const __nv_bfloat16* sBh = sAh + 2*STAGE_H;
        const __nv_bfloat16* sBl = sAh + 3*STAGE_H;

        #pragma unroll
        for (int ks = 0; ks < 32; ks += 16) {
            uint32_t ah[4][4], al[4][4], bh[4][2], bl[4][2];
            const int c0 = ks + 2*qid, c1 = ks + 2*qid + 8;
            #pragma unroll
            for (int mt = 0; mt < 4; mt++) {
                const int r0 = (mb + mt*16 + grp) * LDT;
                const int r1 = r0 + 8*LDT;
                ah[mt][0] = *reinterpret_cast<const uint32_t*>(&sAh[r0 + c0]);
                ah[mt][1] = *reinterpret_cast<const uint32_t*>(&sAh[r1 + c0]);
                ah[mt][2] = *reinterpret_cast<const uint32_t*>(&sAh[r0 + c1]);
                ah[mt][3] = *reinterpret_cast<const uint32_t*>(&sAh[r1 + c1]);
                al[mt][0] = *reinterpret_cast<const uint32_t*>(&sAl[r0 + c0]);
                al[mt][1] = *reinterpret_cast<const uint32_t*>(&sAl[r1 + c0]);
                al[mt][2] = *reinterpret_cast<const uint32_t*>(&sAl[r0 + c1]);
                al[mt][3] = *reinterpret_cast<const uint32_t*>(&sAl[r1 + c1]);
            }
            #pragma unroll
            for (int nt = 0; nt < 4; nt++) {
                const int n0 = (nb + nt*8 + grp) * LDT;
                bh[nt][0] = *reinterpret_cast<const uint32_t*>(&sBh[n0 + c0]);
                bh[nt][1] = *reinterpret_cast<const uint32_t*>(&sBh[n0 + c1]);
                bl[nt][0] = *reinterpret_cast<const uint32_t*>(&sBl[n0 + c0]);
                bl[nt][1] = *reinterpret_cast<const uint32_t*>(&sBl[n0 + c1]);
            }
            #pragma unroll
            for (int mt = 0; mt < 4; mt++)
                #pragma unroll
                for (int nt = 0; nt < 4; nt++) {
                    float* c = acc[mt][nt];
                    asm volatile(
                        "mma.sync.aligned.m16n8k16.row.col.f32.bf16.bf16.f32 "
                        "{%0,%1,%2,%3}, {%4,%5,%6,%7}, {%8,%9}, {%0,%1,%2,%3};\n"
                        : "+f"(c[0]), "+f"(c[1]), "+f"(c[2]), "+f"(c[3])
                        : "r"(ah[mt][0]), "r"(ah[mt][1]), "r"(ah[mt][2]), "r"(ah[mt][3]),
                          "r"(bh[nt][0]), "r"(bh[nt][1]));
                    asm volatile(
                        "mma.sync.aligned.m16n8k16.row.col.f32.bf16.bf16.f32 "
                        "{%0,%1,%2,%3}, {%4,%5,%6,%7}, {%8,%9}, {%0,%1,%2,%3};\n"
                        : "+f"(c[0]), "+f"(c[1]), "+f"(c[2]), "+f"(c[3])
                        : "r"(ah[mt][0]), "r"(ah[mt][1]), "r"(ah[mt][2]), "r"(ah[mt][3]),
                          "r"(bl[nt][0]), "r"(bl[nt][1]));
                    asm volatile(
                        "mma.sync.aligned.m16n8k16.row.col.f32.bf16.bf16.f32 "
                        "{%0,%1,%2,%3}, {%4,%5,%6,%7}, {%8,%9}, {%0,%1,%2,%3};\n"
                        : "+f"(c[0]), "+f"(c[1]), "+f"(c[2]), "+f"(c[3])
                        : "r"(al[mt][0]), "r"(al[mt][1]), "r"(al[mt][2]), "r"(al[mt][3]),
                          "r"(bh[nt][0]), "r"(bh[nt][1]));
                }
        }
        __syncthreads();
    }

    // ---------------- epilogue ----------------
    #pragma unroll
    for (int mt = 0; mt < 4; mt++) {
        const size_t r0 = (size_t)block_row + mb + mt*16 + grp;
        const size_t r1 = r0 + 8;
        #pragma unroll
        for (int nt = 0; nt < 4; nt++) {
            const int col = block_col + nb + nt*8 + 2*qid;
            const float* c = acc[mt][nt];
            if constexpr (EPI == 5) {
                const size_t i0 = r0 * 4096 + col;
                const size_t i1 = r1 * 4096 + col;
                if (blockIdx.x < 8) {
                    *reinterpret_cast<float2*>(C + i0) =
                        make_float2(1.f/(1.f+expf(-c[0])), 1.f/(1.f+expf(-c[1])));
                    *reinterpret_cast<float2*>(C + i1) =
                        make_float2(1.f/(1.f+expf(-c[2])), 1.f/(1.f+expf(-c[3])));
                } else {
                    *reinterpret_cast<float2*>(C + i0) = make_float2(c[0], c[1]);
                    *reinterpret_cast<float2*>(C + i1) = make_float2(c[2], c[3]);
                }
            } else if constexpr (EPI == 6) {
                if (blockIdx.x < 8) {
                    const size_t i0 = r0 * 1024 + col;
                    const size_t i1 = r1 * 1024 + col;
                    *reinterpret_cast<float2*>(C + i0) =
                        make_float2(1.f/(1.f+expf(-c[0])), 1.f/(1.f+expf(-c[1])));
                    *reinterpret_cast<float2*>(C + i1) =
                        make_float2(1.f/(1.f+expf(-c[2])), 1.f/(1.f+expf(-c[3])));
                } else {
                    const size_t i0 = r0 * 4096 + (col - 1024);
                    const size_t i1 = r1 * 4096 + (col - 1024);
                    float t0 = fmaxf(c[0],0.f), t1 = fmaxf(c[1],0.f);
                    float t2 = fmaxf(c[2],0.f), t3 = fmaxf(c[3],0.f);
                    float q0 = t0*t0, q1 = t1*t1, q2 = t2*t2, q3 = t3*t3;
                    __nv_bfloat16 h0=__float2bfloat16(q0), h1=__float2bfloat16(q1);
                    __nv_bfloat16 h2=__float2bfloat16(q2), h3=__float2bfloat16(q3);
                    __nv_bfloat16 l0=__float2bfloat16(q0-__bfloat162float(h0));
                    __nv_bfloat16 l1=__float2bfloat16(q1-__bfloat162float(h1));
                    __nv_bfloat16 l2=__float2bfloat16(q2-__bfloat162float(h2));
                    __nv_bfloat16 l3=__float2bfloat16(q3-__bfloat162float(h3));
                    *reinterpret_cast<uint32_t*>(&Ch[i0]) = packbf(h0,h1);
                    *reinterpret_cast<uint32_t*>(&Ch[i1]) = packbf(h2,h3);
                    *reinterpret_cast<uint32_t*>(&Cl[i0]) = packbf(l0,l1);
                    *reinterpret_cast<uint32_t*>(&Cl[i1]) = packbf(l2,l3);
                }
            } else {
                const size_t i0 = r0 * (size_t)N + col;
                const size_t i1 = r1 * (size_t)N + col;
                float2 o0, o1;
                if constexpr (EPI == 3) {
                    const float2 rr0 = *reinterpret_cast<const float2*>(R + i0);
                    const float2 rr1 = *reinterpret_cast<const float2*>(R + i1);
                    o0 = make_float2(c[0] + rr0.x, c[1] + rr0.y);
                    o1 = make_float2(c[2] + rr1.x, c[3] + rr1.y);
                } else { // EPI 4
                    const float2 rr0 = *reinterpret_cast<const float2*>(R + i0);
                    const float2 rr1 = *reinterpret_cast<const float2*>(R + i1);
                    const float2 mm0 = *reinterpret_cast<const float2*>(MUL + i0);
                    const float2 mm1 = *reinterpret_cast<const float2*>(MUL + i1);
                    o0 = make_float2(rr0.x + mm0.x*c[0], rr0.y + mm0.y*c[1]);
                    o1 = make_float2(rr1.x + mm1.x*c[2], rr1.y + mm1.y*c[3]);
                }
                *reinterpret_cast<float2*>(C + i0) = o0;
                *reinterpret_cast<float2*>(C + i1) = o1;
            }
        }
    }
    #undef LOADSTAGE
}

// ---------------- chunked WKV scan ----------------
// act layout: [M, 4096] = [r | w | k | v]
__global__ void scan_p1(const float* __restrict__ act, const float* __restrict__ td,
                        float* __restrict__ loc)
{
    const int idx = blockIdx.x * blockDim.x + threadIdx.x;
    const int c  = idx >> 12;
    const int bd = idx & 4095;
    const int b  = bd >> 10;
    const int d  = bd & 1023;
    const float decay = expf(td[d]);
    float num = 0.f, den = 0.f;
    const size_t rowbase = (size_t)(b * Sq + c * CL);
    #pragma unroll 2
    for (int s = 0; s < CL; s++) {
        const float* row = act + (rowbase + s) * 4096;
        const float e = expf(row[2048 + d] - expf(row[1024 + d]));
        num = fmaf(decay, num, e * row[3072 + d]);
        den = fmaf(decay, den, e);
    }
    const size_t ci = ((size_t)c * Bq + b) * 2 * Dq + d;
    loc[ci]      = num;
    loc[ci + Dq] = den;
}

// p3: fold carries locally, rescan, fuse r*wkv + bf16 split; writes state.
__global__ void scan_p3(const float* __restrict__ act, const float* __restrict__ td,
                        const float* __restrict__ loc,
                        __nv_bfloat16* __restrict__ rwh, __nv_bfloat16* __restrict__ rwl,
                        float* __restrict__ state, int write_state)
{
    const int idx = blockIdx.x * blockDim.x + threadIdx.x;
    const int c  = idx >> 12;
    const int bd = idx & 4095;
    const int b  = bd >> 10;
    const int d  = bd & 1023;
    const float decay = expf(td[d]);
    const float dl    = expf(td[d] * (float)CL);
    float num = 0.f, den = 0.f;
    for (int cc = 0; cc < c; cc++) {
        const size_t ci = ((size_t)cc * Bq + b) * 2 * Dq + d;
        num = dl * num + loc[ci];
        den = dl * den + loc[ci + Dq];
    }
    const size_t rowbase = (size_t)(b * Sq + c * CL);
    #pragma unroll 2
    for (int s = 0; s < CL; s++) {
        const float* row = act + (rowbase + s) * 4096;
        const float e = expf(row[2048 + d] - expf(row[1024 + d]));
        num = fmaf(decay, num, e * row[3072 + d]);
        den = fmaf(decay, den, e);
        const float rw = row[d] * (num / (den + 1e-8f));
        const __nv_bfloat16 h = __float2bfloat16(rw);
        const __nv_bfloat16 l = __float2bfloat16(rw - __bfloat162float(h));
        const size_t oi = (rowbase + s) * 1024 + d;
        rwh[oi] = h; rwl[oi] = l;
    }
    if (write_state && c == CH - 1) {
        state[(size_t)b*2*Dq + d]      = num;
        state[(size_t)b*2*Dq + Dq + d] = den;
    }
}

// ---------------- launch ----------------
extern "C" void kernel_launch(void* const* d_in, const int* in_sizes, int n_in,
                              void* d_out, int out_size)
{
    (void)in_sizes; (void)n_in;
    const float* x     = (const float*)d_in[0];
    const float* ln1_g = (const float*)d_in[1];
    const float* ln1_b = (const float*)d_in[2];
    const float* ln2_g = (const float*)d_in[3];
    const float* ln2_b = (const float*)d_in[4];
    const float* Wr    = (const float*)d_in[5];
    const float* Ww    = (const float*)d_in[6];
    const float* Wk    = (const float*)d_in[7];
    const float* Wv    = (const float*)d_in[8];
    const float* Wo    = (const float*)d_in[9];
    const float* td    = (const float*)d_in[10];
    const float* Wkey  = (const float*)d_in[12];
    const float* Wval  = (const float*)d_in[13];
    const float* Wrec  = (const float*)d_in[14];

    __nv_bfloat16 *xnh,*xnl,*wqh,*wql,*woh,*wol,*wrkh,*wrkl,*wvalh,*wvall,*rwh,*rwl,*k2h,*k2l;
    float *act,*x1,*r2,*loc;
    cudaGetSymbolAddress((void**)&xnh, g_xnh);     cudaGetSymbolAddress((void**)&xnl, g_xnl);
    cudaGetSymbolAddress((void**)&wqh, g_wqkvwh);  cudaGetSymbolAddress((void**)&wql, g_wqkvwl);
    cudaGetSymbolAddress((void**)&woh, g_woh);     cudaGetSymbolAddress((void**)&wol, g_wol);
    cudaGetSymbolAddress((void**)&wrkh, g_wrkh);   cudaGetSymbolAddress((void**)&wrkl, g_wrkl);
    cudaGetSymbolAddress((void**)&wvalh, g_wvalh); cudaGetSymbolAddress((void**)&wvall, g_wvall);
    cudaGetSymbolAddress((void**)&rwh, g_rwh);     cudaGetSymbolAddress((void**)&rwl, g_rwl);
    cudaGetSymbolAddress((void**)&k2h, g_k2h);     cudaGetSymbolAddress((void**)&k2l, g_k2l);
    cudaGetSymbolAddress((void**)&act, g_act);     cudaGetSymbolAddress((void**)&x1, g_x1);
    cudaGetSymbolAddress((void**)&r2, g_r2);       cudaGetSymbolAddress((void**)&loc, g_loc);

    float* xout = (float*)d_out;
    const int write_state = (out_size >= Mq*Dq + Bq*2*Dq) ? 1 : 0;
    float* state = xout + (size_t)Mq*Dq;

    cudaFuncSetAttribute(mma_gemm<3>, cudaFuncAttributeMaxDynamicSharedMemorySize, SMEM_BYTES);
    cudaFuncSetAttribute(mma_gemm<4>, cudaFuncAttributeMaxDynamicSharedMemorySize, SMEM_BYTES);
    cudaFuncSetAttribute(mma_gemm<5>, cudaFuncAttributeMaxDynamicSharedMemorySize, SMEM_BYTES);
    cudaFuncSetAttribute(mma_gemm<6>, cudaFuncAttributeMaxDynamicSharedMemorySize, SMEM_BYTES);

    const int nDD4 = Dq*Dq/4, nFD4 = Fq*Dq/4;

    // [1] ln1
    ln_split_kernel<<<Mq, 256>>>(x, ln1_g, ln1_b, (uint2*)xnh, (uint2*)xnl);

    // [2] all weight splits in one launch
    SplitJobs js;
    js.j[0] = { (const float4*)Wr,   (uint2*)(wqh + 0*(size_t)Dq*Dq), (uint2*)(wql + 0*(size_t)Dq*Dq), nDD4 };
    js.j[1] = { (const float4*)Ww,   (uint2*)(wqh + 1*(size_t)Dq*Dq), (uint2*)(wql + 1*(size_t)Dq*Dq), nDD4 };
    js.j[2] = { (const float4*)Wk,   (uint2*)(wqh + 2*(size_t)Dq*Dq), (uint2*)(wql + 2*(size_t)Dq*Dq), nDD4 };
    js.j[3] = { (const float4*)Wv,   (uint2*)(wqh + 3*(size_t)Dq*Dq), (uint2*)(wql + 3*(size_t)Dq*Dq), nDD4 };
    js.j[4] = { (const float4*)Wo,   (uint2*)woh,                     (uint2*)wol,                     nDD4 };
    js.j[5] = { (const float4*)Wrec, (uint2*)wrkh,                    (uint2*)wrkl,                    nDD4 };
    js.j[6] = { (const float4*)Wkey, (uint2*)(wrkh + (size_t)Dq*Dq),  (uint2*)(wrkl + (size_t)Dq*Dq),  nFD4 };
    js.j[7] = { (const float4*)Wval, (uint2*)wvalh,                   (uint2*)wvall,                   nFD4 };
    splitall_kernel<<<dim3(nFD4/256, 8), 256>>>(js);

    // [3] fused r|w|k|v GEMM: [M,4096]
    mma_gemm<5><<<dim3(32, 64), 256, SMEM_BYTES>>>(xnh, xnl, wqh, wql,
        act, nullptr, nullptr, nullptr, nullptr, 4096, Dq);
    // [4] scan local
    scan_p1<<<(CH*Bq*Dq)/256, 256>>>(act, td, loc);
    // [5] scan rescan + r*wkv + split
    scan_p3<<<(CH*Bq*Dq)/256, 256>>>(act, td, loc, rwh, rwl, state, write_state);
    // [6] Wo GEMM: x1 = x + (r*wkv)@Wo^T
    mma_gemm<3><<<dim3(8, 64), 256, SMEM_BYTES>>>(rwh, rwl, woh, wol,
        x1, nullptr, nullptr, x, nullptr, 1024, Dq);
    // [7] ln2
    ln_split_kernel<<<Mq, 256>>>(x1, ln2_g, ln2_b, (uint2*)xnh, (uint2*)xnl);
    // [8] fused rec|key GEMM: r2 [M,1024] + k2 [M,4096]
    mma_gemm<6><<<dim3(40, 64), 256, SMEM_BYTES>>>(xnh, xnl, wrkh, wrkl,
        r2, k2h, k2l, nullptr, nullptr, 5120, Dq);
    // [9] Wval GEMM: out = x1 + r2 * (k2@Wval^T)
    mma_gemm<4><<<dim3(8, 64), 256, SMEM_BYTES>>>(k2h, k2l, wvalh, wvall,
        xout, nullptr, nullptr, x1, r2, 1024, Fq);
}

// round 6
// speedup vs baseline: 4.0625x; 1.4074x over previous
#include <cuda_runtime.h>
#include <cuda_fp16.h>
#include <cstdint>
#include <math.h>

#define Bq 4
#define Sq 2048
#define Dq 1024
#define Fq 4096
#define Mq (Bq*Sq)     // 8192
#define CH 32
#define CL (Sq/CH)     // 64
#define LDT 40         // smem row stride in halves (BK=32 + 8 pad)
#define STAGE_H (128*LDT)            // halves per tile (5120)
#define TILES_PER_STAGE 3            // Ah, Al, Bh
#define STG_BYTES (TILES_PER_STAGE*STAGE_H*2)   // 30720
#define NSTAGE 3
#define SMEM_BYTES (NSTAGE*STG_BYTES)           // 92160

// ---------------- scratch ----------------
__device__ __half g_xnh[(size_t)Mq*Dq], g_xnl[(size_t)Mq*Dq];
__device__ __half g_wqkvw[(size_t)4*Dq*Dq];          // [r|w|k|v][D,D] fp16
__device__ __half g_wo[(size_t)Dq*Dq];
__device__ __half g_wrk[(size_t)(Dq+Fq)*Dq];         // [rec|key]
__device__ __half g_wval[(size_t)Dq*Fq];
__device__ float g_act[(size_t)Mq*4*Dq];             // r|w|k|v fp32
__device__ float g_x1 [(size_t)Mq*Dq];
__device__ float g_r2 [(size_t)Mq*Dq];
__device__ __half g_rwh[(size_t)Mq*Dq], g_rwl[(size_t)Mq*Dq];
__device__ __half g_k2h[(size_t)Mq*Fq], g_k2l[(size_t)Mq*Fq];
__device__ float g_loc[(size_t)CH*Bq*2*Dq];

// ---------------- helpers ----------------
__device__ __forceinline__ uint32_t packh(__half a, __half b) {
    __half2 p(a, b);
    return *reinterpret_cast<uint32_t*>(&p);
}
__device__ __forceinline__ void splitA4(float4 v, uint2& h, uint2& l) {
    __half h0 = __float2half(v.x), h1 = __float2half(v.y);
    __half h2 = __float2half(v.z), h3 = __float2half(v.w);
    __half l0 = __float2half(v.x - __half2float(h0));
    __half l1 = __float2half(v.y - __half2float(h1));
    __half l2 = __float2half(v.z - __half2float(h2));
    __half l3 = __float2half(v.w - __half2float(h3));
    h.x = packh(h0,h1); h.y = packh(h2,h3);
    l.x = packh(l0,l1); l.y = packh(l2,l3);
}
__device__ __forceinline__ uint2 cvt4(float4 v) {
    return make_uint2(packh(__float2half(v.x), __float2half(v.y)),
                      packh(__float2half(v.z), __float2half(v.w)));
}

// ---------------- fused weight convert: fp32 -> fp16 (8 matrices, 1 launch) ----
struct CvtJob  { const float4* s; uint2* h; int n4; };
struct CvtJobs { CvtJob j[8]; };
__global__ void cvtall_kernel(CvtJobs js)
{
    const CvtJob jb = js.j[blockIdx.y];
    const int i = blockIdx.x * blockDim.x + threadIdx.x;
    if (i >= jb.n4) return;
    jb.h[i] = cvt4(jb.s[i]);
}

// ---------------- layernorm + fp16 hi/lo split ----------------
__global__ void ln_split_kernel(const float* __restrict__ x,
                                const float* __restrict__ gamma,
                                const float* __restrict__ beta,
                                uint2* __restrict__ oh, uint2* __restrict__ ol)
{
    const int row = blockIdx.x;
    const float4* xr = reinterpret_cast<const float4*>(x) + (size_t)row * (Dq/4);
    float4 v = xr[threadIdx.x];
    float s  = v.x + v.y + v.z + v.w;
    float ss = v.x*v.x + v.y*v.y + v.z*v.z + v.w*v.w;
    #pragma unroll
    for (int o = 16; o > 0; o >>= 1) {
        s  += __shfl_xor_sync(0xffffffffu, s,  o);
        ss += __shfl_xor_sync(0xffffffffu, ss, o);
    }
    __shared__ float rs[8], rss[8];
    const int warp = threadIdx.x >> 5;
    if ((threadIdx.x & 31) == 0) { rs[warp] = s; rss[warp] = ss; }
    __syncthreads();
    float ts = 0.f, tss = 0.f;
    #pragma unroll
    for (int i = 0; i < 8; i++) { ts += rs[i]; tss += rss[i]; }
    const float mu   = ts * (1.0f/Dq);
    const float var  = tss * (1.0f/Dq) - mu*mu;
    const float rstd = rsqrtf(var + 1e-5f);
    const float4 g4 = reinterpret_cast<const float4*>(gamma)[threadIdx.x];
    const float4 b4 = reinterpret_cast<const float4*>(beta )[threadIdx.x];
    float4 o;
    o.x = (v.x - mu)*rstd*g4.x + b4.x;
    o.y = (v.y - mu)*rstd*g4.y + b4.y;
    o.z = (v.z - mu)*rstd*g4.z + b4.z;
    o.w = (v.w - mu)*rstd*g4.w + b4.w;
    uint2 h, l; splitA4(o, h, l);
    const size_t idx = (size_t)row * (Dq/4) + threadIdx.x;
    oh[idx] = h; ol[idx] = l;
}

// ---------------- HMMA GEMM: C[M,N] = f( (Ah+Al)[M,K] @ Bh[N,K]^T ) -----------
// A fp16 hi/lo (exact to 2^-22), B fp16 (error source, ~2^-12 rel).
// 2 MMAs per k16 tile. 3-stage cp.async pipeline, BK=32.
// EPI: 3 = acc + R; 4 = R + MUL*acc; 5 = qkvw (col<1024 sigmoid, else raw; N=4096)
//      6 = rec|key (col<1024 sigmoid->C[M,1024]; else relu^2 -> Ch/Cl fp16 [M,4096])
template<int EPI>
__global__ void __launch_bounds__(256)
mma_gemm(const __half* __restrict__ Ah, const __half* __restrict__ Al,
         const __half* __restrict__ Bh,
         float* __restrict__ C, __half* __restrict__ Ch, __half* __restrict__ Cl,
         const float* __restrict__ R, const float* __restrict__ MUL,
         int N, int K)
{
    extern __shared__ __half dyn[];

    const int tid = threadIdx.x;
    const int block_row = blockIdx.y * 128;
    const int block_col = blockIdx.x * 128;

    const uint32_t sbase = (uint32_t)__cvta_generic_to_shared(dyn);

    // loaders: 2 threads per row, each 2 x 16B per tile
    const int lr = tid >> 1;
    const int sg = (tid & 1) * 2;
    const __half* gA_h = Ah + (size_t)(block_row + lr) * K;
    const __half* gA_l = Al + (size_t)(block_row + lr) * K;
    const __half* gB_h = Bh + (size_t)(block_col + lr) * K;
    const uint32_t srow = sbase + (uint32_t)(lr * LDT) * 2;

    #define LOADSTAGE(st, ko)                                                          \
    do {                                                                               \
        const uint32_t sb = srow + (uint32_t)(st) * STG_BYTES;                         \
        _Pragma("unroll")                                                              \
        for (int j = 0; j < 2; j++) {                                                  \
            const int sj = sg + j;                                                     \
            const uint32_t co = (uint32_t)sj * 16;                                     \
            asm volatile("cp.async.cg.shared.global [%0], [%1], 16;" ::                \
                "r"(sb + 0*STAGE_H*2 + co), "l"(gA_h + (ko) + sj*8));                  \
            asm volatile("cp.async.cg.shared.global [%0], [%1], 16;" ::                \
                "r"(sb + 1*STAGE_H*2 + co), "l"(gA_l + (ko) + sj*8));                  \
            asm volatile("cp.async.cg.shared.global [%0], [%1], 16;" ::                \
                "r"(sb + 2*STAGE_H*2 + co), "l"(gB_h + (ko) + sj*8));                  \
        }                                                                              \
        asm volatile("cp.async.commit_group;" ::: "memory");                           \
    } while (0)

    const int lane = tid & 31;
    const int wm = (tid >> 7);
    const int wn = (tid >> 5) & 3;
    const int grp = lane >> 2, qid = lane & 3;
    const int mb = wm * 64, nb = wn * 32;

    float acc[4][4][4];
    #pragma unroll
    for (int i = 0; i < 4; i++)
        #pragma unroll
        for (int j = 0; j < 4; j++)
            #pragma unroll
            for (int q = 0; q < 4; q++) acc[i][j][q] = 0.f;

    const int KT = K >> 5;
    LOADSTAGE(0, 0);
    LOADSTAGE(1, 32);

    for (int kt = 0; kt < KT; kt++) {
        const int st = kt % NSTAGE;
        if (kt + 1 < KT) asm volatile("cp.async.wait_group 1;" ::: "memory");
        else             asm volatile("cp.async.wait_group 0;" ::: "memory");
        __syncthreads();
        if (kt + 2 < KT) LOADSTAGE((kt + 2) % NSTAGE, (kt + 2) * 32);

        const __half* sAh = dyn + st * (TILES_PER_STAGE*STAGE_H);
        const __half* sAl = sAh + STAGE_H;
        const __half* sBh = sAh + 2*STAGE_H;

        #pragma unroll
        for (int ks = 0; ks < 32; ks += 16) {
            uint32_t ah[4][4], al[4][4], bh[4][2];
            const int c0 = ks + 2*qid, c1 = ks + 2*qid + 8;
            #pragma unroll
            for (int mt = 0; mt < 4; mt++) {
                const int r0 = (mb + mt*16 + grp) * LDT;
                const int r1 = r0 + 8*LDT;
                ah[mt][0] = *reinterpret_cast<const uint32_t*>(&sAh[r0 + c0]);
                ah[mt][1] = *reinterpret_cast<const uint32_t*>(&sAh[r1 + c0]);
                ah[mt][2] = *reinterpret_cast<const uint32_t*>(&sAh[r0 + c1]);
                ah[mt][3] = *reinterpret_cast<const uint32_t*>(&sAh[r1 + c1]);
                al[mt][0] = *reinterpret_cast<const uint32_t*>(&sAl[r0 + c0]);
                al[mt][1] = *reinterpret_cast<const uint32_t*>(&sAl[r1 + c0]);
                al[mt][2] = *reinterpret_cast<const uint32_t*>(&sAl[r0 + c1]);
                al[mt][3] = *reinterpret_cast<const uint32_t*>(&sAl[r1 + c1]);
            }
            #pragma unroll
            for (int nt = 0; nt < 4; nt++) {
                const int n0 = (nb + nt*8 + grp) * LDT;
                bh[nt][0] = *reinterpret_cast<const uint32_t*>(&sBh[n0 + c0]);
                bh[nt][1] = *reinterpret_cast<const uint32_t*>(&sBh[n0 + c1]);
            }
            #pragma unroll
            for (int mt = 0; mt < 4; mt++)
                #pragma unroll
                for (int nt = 0; nt < 4; nt++) {
                    float* c = acc[mt][nt];
                    asm volatile(
                        "mma.sync.aligned.m16n8k16.row.col.f32.f16.f16.f32 "
                        "{%0,%1,%2,%3}, {%4,%5,%6,%7}, {%8,%9}, {%0,%1,%2,%3};\n"
                        : "+f"(c[0]), "+f"(c[1]), "+f"(c[2]), "+f"(c[3])
                        : "r"(ah[mt][0]), "r"(ah[mt][1]), "r"(ah[mt][2]), "r"(ah[mt][3]),
                          "r"(bh[nt][0]), "r"(bh[nt][1]));
                    asm volatile(
                        "mma.sync.aligned.m16n8k16.row.col.f32.f16.f16.f32 "
                        "{%0,%1,%2,%3}, {%4,%5,%6,%7}, {%8,%9}, {%0,%1,%2,%3};\n"
                        : "+f"(c[0]), "+f"(c[1]), "+f"(c[2]), "+f"(c[3])
                        : "r"(al[mt][0]), "r"(al[mt][1]), "r"(al[mt][2]), "r"(al[mt][3]),
                          "r"(bh[nt][0]), "r"(bh[nt][1]));
                }
        }
        __syncthreads();
    }

    // ---------------- epilogue ----------------
    #pragma unroll
    for (int mt = 0; mt < 4; mt++) {
        const size_t r0 = (size_t)block_row + mb + mt*16 + grp;
        const size_t r1 = r0 + 8;
        #pragma unroll
        for (int nt = 0; nt < 4; nt++) {
            const int col = block_col + nb + nt*8 + 2*qid;
            const float* c = acc[mt][nt];
            if constexpr (EPI == 5) {
                const size_t i0 = r0 * 4096 + col;
                const size_t i1 = r1 * 4096 + col;
                if (blockIdx.x < 8) {
                    *reinterpret_cast<float2*>(C + i0) =
                        make_float2(1.f/(1.f+expf(-c[0])), 1.f/(1.f+expf(-c[1])));
                    *reinterpret_cast<float2*>(C + i1) =
                        make_float2(1.f/(1.f+expf(-c[2])), 1.f/(1.f+expf(-c[3])));
                } else {
                    *reinterpret_cast<float2*>(C + i0) = make_float2(c[0], c[1]);
                    *reinterpret_cast<float2*>(C + i1) = make_float2(c[2], c[3]);
                }
            } else if constexpr (EPI == 6) {
                if (blockIdx.x < 8) {
                    const size_t i0 = r0 * 1024 + col;
                    const size_t i1 = r1 * 1024 + col;
                    *reinterpret_cast<float2*>(C + i0) =
                        make_float2(1.f/(1.f+expf(-c[0])), 1.f/(1.f+expf(-c[1])));
                    *reinterpret_cast<float2*>(C + i1) =
                        make_float2(1.f/(1.f+expf(-c[2])), 1.f/(1.f+expf(-c[3])));
                } else {
                    const size_t i0 = r0 * 4096 + (col - 1024);
                    const size_t i1 = r1 * 4096 + (col - 1024);
                    float t0 = fmaxf(c[0],0.f), t1 = fmaxf(c[1],0.f);
                    float t2 = fmaxf(c[2],0.f), t3 = fmaxf(c[3],0.f);
                    float q0 = t0*t0, q1 = t1*t1, q2 = t2*t2, q3 = t3*t3;
                    __half h0=__float2half(q0), h1=__float2half(q1);
                    __half h2=__float2half(q2), h3=__float2half(q3);
                    __half l0=__float2half(q0-__half2float(h0));
                    __half l1=__float2half(q1-__half2float(h1));
                    __half l2=__float2half(q2-__half2float(h2));
                    __half l3=__float2half(q3-__half2float(h3));
                    *reinterpret_cast<uint32_t*>(&Ch[i0]) = packh(h0,h1);
                    *reinterpret_cast<uint32_t*>(&Ch[i1]) = packh(h2,h3);
                    *reinterpret_cast<uint32_t*>(&Cl[i0]) = packh(l0,l1);
                    *reinterpret_cast<uint32_t*>(&Cl[i1]) = packh(l2,l3);
                }
            } else {
                const size_t i0 = r0 * (size_t)N + col;
                const size_t i1 = r1 * (size_t)N + col;
                float2 o0, o1;
                if constexpr (EPI == 3) {
                    const float2 rr0 = *reinterpret_cast<const float2*>(R + i0);
                    const float2 rr1 = *reinterpret_cast<const float2*>(R + i1);
                    o0 = make_float2(c[0] + rr0.x, c[1] + rr0.y);
                    o1 = make_float2(c[2] + rr1.x, c[3] + rr1.y);
                } else { // EPI 4
                    const float2 rr0 = *reinterpret_cast<const float2*>(R + i0);
                    const float2 rr1 = *reinterpret_cast<const float2*>(R + i1);
                    const float2 mm0 = *reinterpret_cast<const float2*>(MUL + i0);
                    const float2 mm1 = *reinterpret_cast<const float2*>(MUL + i1);
                    o0 = make_float2(rr0.x + mm0.x*c[0], rr0.y + mm0.y*c[1]);
                    o1 = make_float2(rr1.x + mm1.x*c[2], rr1.y + mm1.y*c[3]);
                }
                *reinterpret_cast<float2*>(C + i0) = o0;
                *reinterpret_cast<float2*>(C + i1) = o1;
            }
        }
    }
    #undef LOADSTAGE
}

// ---------------- chunked WKV scan (act = [M,4096] = [r|w|k|v]) --------------
__global__ void scan_p1(const float* __restrict__ act, const float* __restrict__ td,
                        float* __restrict__ loc)
{
    const int idx = blockIdx.x * blockDim.x + threadIdx.x;
    const int c  = idx >> 12;
    const int bd = idx & 4095;
    const int b  = bd >> 10;
    const int d  = bd & 1023;
    const float decay = expf(td[d]);
    float num = 0.f, den = 0.f;
    const size_t rowbase = (size_t)(b * Sq + c * CL);
    #pragma unroll 2
    for (int s = 0; s < CL; s++) {
        const float* row = act + (rowbase + s) * 4096;
        const float e = expf(row[2048 + d] - expf(row[1024 + d]));
        num = fmaf(decay, num, e * row[3072 + d]);
        den = fmaf(decay, den, e);
    }
    const size_t ci = ((size_t)c * Bq + b) * 2 * Dq + d;
    loc[ci]      = num;
    loc[ci + Dq] = den;
}

__global__ void scan_p3(const float* __restrict__ act, const float* __restrict__ td,
                        const float* __restrict__ loc,
                        __half* __restrict__ rwh, __half* __restrict__ rwl,
                        float* __restrict__ state, int write_state)
{
    const int idx = blockIdx.x * blockDim.x + threadIdx.x;
    const int c  = idx >> 12;
    const int bd = idx & 4095;
    const int b  = bd >> 10;
    const int d  = bd & 1023;
    const float decay = expf(td[d]);
    const float dl    = expf(td[d] * (float)CL);
    float num = 0.f, den = 0.f;
    for (int cc = 0; cc < c; cc++) {
        const size_t ci = ((size_t)cc * Bq + b) * 2 * Dq + d;
        num = dl * num + loc[ci];
        den = dl * den + loc[ci + Dq];
    }
    const size_t rowbase = (size_t)(b * Sq + c * CL);
    #pragma unroll 2
    for (int s = 0; s < CL; s++) {
        const float* row = act + (rowbase + s) * 4096;
        const float e = expf(row[2048 + d] - expf(row[1024 + d]));
        num = fmaf(decay, num, e * row[3072 + d]);
        den = fmaf(decay, den, e);
        const float rw = row[d] * (num / (den + 1e-8f));
        const __half h = __float2half(rw);
        const __half l = __float2half(rw - __half2float(h));
        const size_t oi = (rowbase + s) * 1024 + d;
        rwh[oi] = h; rwl[oi] = l;
    }
    if (write_state && c == CH - 1) {
        state[(size_t)b*2*Dq + d]      = num;
        state[(size_t)b*2*Dq + Dq + d] = den;
    }
}

// ---------------- launch ----------------
extern "C" void kernel_launch(void* const* d_in, const int* in_sizes, int n_in,
                              void* d_out, int out_size)
{
    (void)in_sizes; (void)n_in;
    const float* x     = (const float*)d_in[0];
    const float* ln1_g = (const float*)d_in[1];
    const float* ln1_b = (const float*)d_in[2];
    const float* ln2_g = (const float*)d_in[3];
    const float* ln2_b = (const float*)d_in[4];
    const float* Wr    = (const float*)d_in[5];
    const float* Ww    = (const float*)d_in[6];
    const float* Wk    = (const float*)d_in[7];
    const float* Wv    = (const float*)d_in[8];
    const float* Wo    = (const float*)d_in[9];
    const float* td    = (const float*)d_in[10];
    const float* Wkey  = (const float*)d_in[12];
    const float* Wval  = (const float*)d_in[13];
    const float* Wrec  = (const float*)d_in[14];

    __half *xnh,*xnl,*wq,*wo,*wrk,*wval,*rwh,*rwl,*k2h,*k2l;
    float *act,*x1,*r2,*loc;
    cudaGetSymbolAddress((void**)&xnh, g_xnh);   cudaGetSymbolAddress((void**)&xnl, g_xnl);
    cudaGetSymbolAddress((void**)&wq, g_wqkvw);  cudaGetSymbolAddress((void**)&wo, g_wo);
    cudaGetSymbolAddress((void**)&wrk, g_wrk);   cudaGetSymbolAddress((void**)&wval, g_wval);
    cudaGetSymbolAddress((void**)&rwh, g_rwh);   cudaGetSymbolAddress((void**)&rwl, g_rwl);
    cudaGetSymbolAddress((void**)&k2h, g_k2h);   cudaGetSymbolAddress((void**)&k2l, g_k2l);
    cudaGetSymbolAddress((void**)&act, g_act);   cudaGetSymbolAddress((void**)&x1, g_x1);
    cudaGetSymbolAddress((void**)&r2, g_r2);     cudaGetSymbolAddress((void**)&loc, g_loc);

    float* xout = (float*)d_out;
    const int write_state = (out_size >= Mq*Dq + Bq*2*Dq) ? 1 : 0;
    float* state = xout + (size_t)Mq*Dq;

    cudaFuncSetAttribute(mma_gemm<3>, cudaFuncAttributeMaxDynamicSharedMemorySize, SMEM_BYTES);
    cudaFuncSetAttribute(mma_gemm<4>, cudaFuncAttributeMaxDynamicSharedMemorySize, SMEM_BYTES);
    cudaFuncSetAttribute(mma_gemm<5>, cudaFuncAttributeMaxDynamicSharedMemorySize, SMEM_BYTES);
    cudaFuncSetAttribute(mma_gemm<6>, cudaFuncAttributeMaxDynamicSharedMemorySize, SMEM_BYTES);

    const int nDD4 = Dq*Dq/4, nFD4 = Fq*Dq/4;

    // [1] ln1
    ln_split_kernel<<<Mq, 256>>>(x, ln1_g, ln1_b, (uint2*)xnh, (uint2*)xnl);

    // [2] all weight converts (fp32 -> fp16) in one launch
    CvtJobs js;
    js.j[0] = { (const float4*)Wr,   (uint2*)(wq + 0*(size_t)Dq*Dq), nDD4 };
    js.j[1] = { (const float4*)Ww,   (uint2*)(wq + 1*(size_t)Dq*Dq), nDD4 };
    js.j[2] = { (const float4*)Wk,   (uint2*)(wq + 2*(size_t)Dq*Dq), nDD4 };
    js.j[3] = { (const float4*)Wv,   (uint2*)(wq + 3*(size_t)Dq*Dq), nDD4 };
    js.j[4] = { (const float4*)Wo,   (uint2*)wo,                     nDD4 };
    js.j[5] = { (const float4*)Wrec, (uint2*)wrk,                    nDD4 };
    js.j[6] = { (const float4*)Wkey, (uint2*)(wrk + (size_t)Dq*Dq),  nFD4 };
    js.j[7] = { (const float4*)Wval, (uint2*)wval,                   nFD4 };
    cvtall_kernel<<<dim3(nFD4/256, 8), 256>>>(js);

    // [3] fused r|w|k|v GEMM -> act [M,4096]
    mma_gemm<5><<<dim3(32, 64), 256, SMEM_BYTES>>>(xnh, xnl, wq,
        act, nullptr, nullptr, nullptr, nullptr, 4096, Dq);
    // [4][5] scan
    scan_p1<<<(CH*Bq*Dq)/256, 256>>>(act, td, loc);
    scan_p3<<<(CH*Bq*Dq)/256, 256>>>(act, td, loc, rwh, rwl, state, write_state);
    // [6] Wo GEMM: x1 = x + (r*wkv)@Wo^T
    mma_gemm<3><<<dim3(8, 64), 256, SMEM_BYTES>>>(rwh, rwl, wo,
        x1, nullptr, nullptr, x, nullptr, 1024, Dq);
    // [7] ln2
    ln_split_kernel<<<Mq, 256>>>(x1, ln2_g, ln2_b, (uint2*)xnh, (uint2*)xnl);
    // [8] fused rec|key GEMM: r2 [M,1024] + k2 hi/lo [M,4096]
    mma_gemm<6><<<dim3(40, 64), 256, SMEM_BYTES>>>(xnh, xnl, wrk,
        r2, k2h, k2l, nullptr, nullptr, 5120, Dq);
    // [9] Wval GEMM: out = x1 + r2*(k2@Wval^T)
    mma_gemm<4><<<dim3(8, 64), 256, SMEM_BYTES>>>(k2h, k2l, wval,
        xout, nullptr, nullptr, x1, r2, 1024, Fq);
}

// round 7
// speedup vs baseline: 6.3781x; 1.5700x over previous
#include <cuda_runtime.h>
#include <cuda_fp16.h>
#include <cstdint>
#include <math.h>

#define Bq 4
#define Sq 2048
#define Dq 1024
#define Fq 4096
#define Mq (Bq*Sq)     // 8192
#define CH 32
#define CL (Sq/CH)     // 64
#define LDT 40         // smem row stride in halves (BK=32 + 8 pad)
#define STAGE_H (128*LDT)            // halves per tile (5120)
#define TILES_PER_STAGE 2            // A, B
#define STG_BYTES (TILES_PER_STAGE*STAGE_H*2)   // 20480
#define NSTAGE 4
#define SMEM_BYTES (NSTAGE*STG_BYTES)           // 81920

// ---------------- scratch ----------------
__device__ __half g_xn[(size_t)Mq*Dq];
__device__ __half g_wqkvw[(size_t)4*Dq*Dq];          // [r|w|k|v][D,D] fp16
__device__ __half g_wo[(size_t)Dq*Dq];
__device__ __half g_wrk[(size_t)(Dq+Fq)*Dq];         // [rec|key]
__device__ __half g_wval[(size_t)Dq*Fq];
__device__ float g_act[(size_t)Mq*4*Dq];             // r|w|k|v fp32
__device__ float g_x1 [(size_t)Mq*Dq];
__device__ float g_r2 [(size_t)Mq*Dq];
__device__ __half g_rw[(size_t)Mq*Dq];
__device__ __half g_k2[(size_t)Mq*Fq];
__device__ float g_loc[(size_t)CH*Bq*2*Dq];

// ---------------- helpers ----------------
__device__ __forceinline__ uint32_t packh(__half a, __half b) {
    __half2 p(a, b);
    return *reinterpret_cast<uint32_t*>(&p);
}
__device__ __forceinline__ uint2 cvt4(float4 v) {
    return make_uint2(packh(__float2half(v.x), __float2half(v.y)),
                      packh(__float2half(v.z), __float2half(v.w)));
}

// ---------------- fused weight convert: fp32 -> fp16 (8 matrices, 1 launch) ----
struct CvtJob  { const float4* s; uint2* h; int n4; };
struct CvtJobs { CvtJob j[8]; };
__global__ void cvtall_kernel(CvtJobs js)
{
    const CvtJob jb = js.j[blockIdx.y];
    const int i = blockIdx.x * blockDim.x + threadIdx.x;
    if (i >= jb.n4) return;
    jb.h[i] = cvt4(jb.s[i]);
}

// ---------------- layernorm -> fp16 ----------------
__global__ void ln_cvt_kernel(const float* __restrict__ x,
                              const float* __restrict__ gamma,
                              const float* __restrict__ beta,
                              uint2* __restrict__ oh)
{
    const int row = blockIdx.x;
    const float4* xr = reinterpret_cast<const float4*>(x) + (size_t)row * (Dq/4);
    float4 v = xr[threadIdx.x];
    float s  = v.x + v.y + v.z + v.w;
    float ss = v.x*v.x + v.y*v.y + v.z*v.z + v.w*v.w;
    #pragma unroll
    for (int o = 16; o > 0; o >>= 1) {
        s  += __shfl_xor_sync(0xffffffffu, s,  o);
        ss += __shfl_xor_sync(0xffffffffu, ss, o);
    }
    __shared__ float rs[8], rss[8];
    const int warp = threadIdx.x >> 5;
    if ((threadIdx.x & 31) == 0) { rs[warp] = s; rss[warp] = ss; }
    __syncthreads();
    float ts = 0.f, tss = 0.f;
    #pragma unroll
    for (int i = 0; i < 8; i++) { ts += rs[i]; tss += rss[i]; }
    const float mu   = ts * (1.0f/Dq);
    const float var  = tss * (1.0f/Dq) - mu*mu;
    const float rstd = rsqrtf(var + 1e-5f);
    const float4 g4 = reinterpret_cast<const float4*>(gamma)[threadIdx.x];
    const float4 b4 = reinterpret_cast<const float4*>(beta )[threadIdx.x];
    float4 o;
    o.x = (v.x - mu)*rstd*g4.x + b4.x;
    o.y = (v.y - mu)*rstd*g4.y + b4.y;
    o.z = (v.z - mu)*rstd*g4.z + b4.z;
    o.w = (v.w - mu)*rstd*g4.w + b4.w;
    oh[(size_t)row * (Dq/4) + threadIdx.x] = cvt4(o);
}

// ---------------- HMMA GEMM: C[M,N] = f( A[M,K] @ B[N,K]^T ), fp16 in/fp32 acc
// 1 MMA per k16 tile. 4-stage cp.async pipeline, BK=32.
// EPI: 3 = acc + R; 4 = R + MUL*acc; 5 = qkvw (col<1024 sigmoid, else raw; N=4096)
//      6 = rec|key (col<1024 sigmoid->C[M,1024]; else relu^2 -> Ch fp16 [M,4096])
template<int EPI>
__global__ void __launch_bounds__(256)
mma_gemm(const __half* __restrict__ A, const __half* __restrict__ B,
         float* __restrict__ C, __half* __restrict__ Ch,
         const float* __restrict__ R, const float* __restrict__ MUL,
         int N, int K)
{
    extern __shared__ __half dyn[];

    const int tid = threadIdx.x;
    const int block_row = blockIdx.y * 128;
    const int block_col = blockIdx.x * 128;

    const uint32_t sbase = (uint32_t)__cvta_generic_to_shared(dyn);

    // loaders: 2 threads per row, each 2 x 16B per tile
    const int lr = tid >> 1;
    const int sg = (tid & 1) * 2;
    const __half* gA = A + (size_t)(block_row + lr) * K;
    const __half* gB = B + (size_t)(block_col + lr) * K;
    const uint32_t srow = sbase + (uint32_t)(lr * LDT) * 2;

    #define LOADSTAGE(st, ko)                                                          \
    do {                                                                               \
        const uint32_t sb = srow + (uint32_t)(st) * STG_BYTES;                         \
        _Pragma("unroll")                                                              \
        for (int j = 0; j < 2; j++) {                                                  \
            const int sj = sg + j;                                                     \
            const uint32_t co = (uint32_t)sj * 16;                                     \
            asm volatile("cp.async.cg.shared.global [%0], [%1], 16;" ::                \
                "r"(sb + 0*STAGE_H*2 + co), "l"(gA + (ko) + sj*8));                    \
            asm volatile("cp.async.cg.shared.global [%0], [%1], 16;" ::                \
                "r"(sb + 1*STAGE_H*2 + co), "l"(gB + (ko) + sj*8));                    \
        }                                                                              \
        asm volatile("cp.async.commit_group;" ::: "memory");                           \
    } while (0)

    const int lane = tid & 31;
    const int wm = (tid >> 7);
    const int wn = (tid >> 5) & 3;
    const int grp = lane >> 2, qid = lane & 3;
    const int mb = wm * 64, nb = wn * 32;

    float acc[4][4][4];
    #pragma unroll
    for (int i = 0; i < 4; i++)
        #pragma unroll
        for (int j = 0; j < 4; j++)
            #pragma unroll
            for (int q = 0; q < 4; q++) acc[i][j][q] = 0.f;

    const int KT = K >> 5;
    LOADSTAGE(0, 0);
    LOADSTAGE(1, 32);
    LOADSTAGE(2, 64);

    for (int kt = 0; kt < KT; kt++) {
        const int st = kt & (NSTAGE - 1);
        asm volatile("cp.async.wait_group 2;" ::: "memory");
        __syncthreads();
        if (kt + 3 < KT) LOADSTAGE((kt + 3) & (NSTAGE - 1), (kt + 3) * 32);
        else             asm volatile("cp.async.commit_group;" ::: "memory");

        const __half* sA = dyn + st * (TILES_PER_STAGE*STAGE_H);
        const __half* sB = sA + STAGE_H;

        #pragma unroll
        for (int ks = 0; ks < 32; ks += 16) {
            uint32_t ar[4][4], br[4][2];
            const int c0 = ks + 2*qid, c1 = ks + 2*qid + 8;
            #pragma unroll
            for (int mt = 0; mt < 4; mt++) {
                const int r0 = (mb + mt*16 + grp) * LDT;
                const int r1 = r0 + 8*LDT;
                ar[mt][0] = *reinterpret_cast<const uint32_t*>(&sA[r0 + c0]);
                ar[mt][1] = *reinterpret_cast<const uint32_t*>(&sA[r1 + c0]);
                ar[mt][2] = *reinterpret_cast<const uint32_t*>(&sA[r0 + c1]);
                ar[mt][3] = *reinterpret_cast<const uint32_t*>(&sA[r1 + c1]);
            }
            #pragma unroll
            for (int nt = 0; nt < 4; nt++) {
                const int n0 = (nb + nt*8 + grp) * LDT;
                br[nt][0] = *reinterpret_cast<const uint32_t*>(&sB[n0 + c0]);
                br[nt][1] = *reinterpret_cast<const uint32_t*>(&sB[n0 + c1]);
            }
            #pragma unroll
            for (int mt = 0; mt < 4; mt++)
                #pragma unroll
                for (int nt = 0; nt < 4; nt++) {
                    float* c = acc[mt][nt];
                    asm volatile(
                        "mma.sync.aligned.m16n8k16.row.col.f32.f16.f16.f32 "
                        "{%0,%1,%2,%3}, {%4,%5,%6,%7}, {%8,%9}, {%0,%1,%2,%3};\n"
                        : "+f"(c[0]), "+f"(c[1]), "+f"(c[2]), "+f"(c[3])
                        : "r"(ar[mt][0]), "r"(ar[mt][1]), "r"(ar[mt][2]), "r"(ar[mt][3]),
                          "r"(br[nt][0]), "r"(br[nt][1]));
                }
        }
        __syncthreads();
    }

    // ---------------- epilogue ----------------
    #pragma unroll
    for (int mt = 0; mt < 4; mt++) {
        const size_t r0 = (size_t)block_row + mb + mt*16 + grp;
        const size_t r1 = r0 + 8;
        #pragma unroll
        for (int nt = 0; nt < 4; nt++) {
            const int col = block_col + nb + nt*8 + 2*qid;
            const float* c = acc[mt][nt];
            if constexpr (EPI == 5) {
                const size_t i0 = r0 * 4096 + col;
                const size_t i1 = r1 * 4096 + col;
                if (blockIdx.x < 8) {
                    *reinterpret_cast<float2*>(C + i0) =
                        make_float2(1.f/(1.f+expf(-c[0])), 1.f/(1.f+expf(-c[1])));
                    *reinterpret_cast<float2*>(C + i1) =
                        make_float2(1.f/(1.f+expf(-c[2])), 1.f/(1.f+expf(-c[3])));
                } else {
                    *reinterpret_cast<float2*>(C + i0) = make_float2(c[0], c[1]);
                    *reinterpret_cast<float2*>(C + i1) = make_float2(c[2], c[3]);
                }
            } else if constexpr (EPI == 6) {
                if (blockIdx.x < 8) {
                    const size_t i0 = r0 * 1024 + col;
                    const size_t i1 = r1 * 1024 + col;
                    *reinterpret_cast<float2*>(C + i0) =
                        make_float2(1.f/(1.f+expf(-c[0])), 1.f/(1.f+expf(-c[1])));
                    *reinterpret_cast<float2*>(C + i1) =
                        make_float2(1.f/(1.f+expf(-c[2])), 1.f/(1.f+expf(-c[3])));
                } else {
                    const size_t i0 = r0 * 4096 + (col - 1024);
                    const size_t i1 = r1 * 4096 + (col - 1024);
                    float t0 = fmaxf(c[0],0.f), t1 = fmaxf(c[1],0.f);
                    float t2 = fmaxf(c[2],0.f), t3 = fmaxf(c[3],0.f);
                    *reinterpret_cast<uint32_t*>(&Ch[i0]) =
                        packh(__float2half(t0*t0), __float2half(t1*t1));
                    *reinterpret_cast<uint32_t*>(&Ch[i1]) =
                        packh(__float2half(t2*t2), __float2half(t3*t3));
                }
            } else {
                const size_t i0 = r0 * (size_t)N + col;
                const size_t i1 = r1 * (size_t)N + col;
                float2 o0, o1;
                if constexpr (EPI == 3) {
                    const float2 rr0 = *reinterpret_cast<const float2*>(R + i0);
                    const float2 rr1 = *reinterpret_cast<const float2*>(R + i1);
                    o0 = make_float2(c[0] + rr0.x, c[1] + rr0.y);
                    o1 = make_float2(c[2] + rr1.x, c[3] + rr1.y);
                } else { // EPI 4
                    const float2 rr0 = *reinterpret_cast<const float2*>(R + i0);
                    const float2 rr1 = *reinterpret_cast<const float2*>(R + i1);
                    const float2 mm0 = *reinterpret_cast<const float2*>(MUL + i0);
                    const float2 mm1 = *reinterpret_cast<const float2*>(MUL + i1);
                    o0 = make_float2(rr0.x + mm0.x*c[0], rr0.y + mm0.y*c[1]);
                    o1 = make_float2(rr1.x + mm1.x*c[2], rr1.y + mm1.y*c[3]);
                }
                *reinterpret_cast<float2*>(C + i0) = o0;
                *reinterpret_cast<float2*>(C + i1) = o1;
            }
        }
    }
    #undef LOADSTAGE
}

// ---------------- chunked WKV scan (act = [M,4096] = [r|w|k|v]) --------------
__global__ void scan_p1(const float* __restrict__ act, const float* __restrict__ td,
                        float* __restrict__ loc)
{
    const int idx = blockIdx.x * blockDim.x + threadIdx.x;
    const int c  = idx >> 12;
    const int bd = idx & 4095;
    const int b  = bd >> 10;
    const int d  = bd & 1023;
    const float decay = expf(td[d]);
    float num = 0.f, den = 0.f;
    const size_t rowbase = (size_t)(b * Sq + c * CL);
    #pragma unroll 2
    for (int s = 0; s < CL; s++) {
        const float* row = act + (rowbase + s) * 4096;
        const float e = expf(row[2048 + d] - expf(row[1024 + d]));
        num = fmaf(decay, num, e * row[3072 + d]);
        den = fmaf(decay, den, e);
    }
    const size_t ci = ((size_t)c * Bq + b) * 2 * Dq + d;
    loc[ci]      = num;
    loc[ci + Dq] = den;
}

__global__ void scan_p3(const float* __restrict__ act, const float* __restrict__ td,
                        const float* __restrict__ loc,
                        __half* __restrict__ rw,
                        float* __restrict__ state, int write_state)
{
    const int idx = blockIdx.x * blockDim.x + threadIdx.x;
    const int c  = idx >> 12;
    const int bd = idx & 4095;
    const int b  = bd >> 10;
    const int d  = bd & 1023;
    const float decay = expf(td[d]);
    const float dl    = expf(td[d] * (float)CL);
    float num = 0.f, den = 0.f;
    for (int cc = 0; cc < c; cc++) {
        const size_t ci = ((size_t)cc * Bq + b) * 2 * Dq + d;
        num = dl * num + loc[ci];
        den = dl * den + loc[ci + Dq];
    }
    const size_t rowbase = (size_t)(b * Sq + c * CL);
    #pragma unroll 2
    for (int s = 0; s < CL; s++) {
        const float* row = act + (rowbase + s) * 4096;
        const float e = expf(row[2048 + d] - expf(row[1024 + d]));
        num = fmaf(decay, num, e * row[3072 + d]);
        den = fmaf(decay, den, e);
        rw[(rowbase + s) * 1024 + d] =
            __float2half(row[d] * (num / (den + 1e-8f)));
    }
    if (write_state && c == CH - 1) {
        state[(size_t)b*2*Dq + d]      = num;
        state[(size_t)b*2*Dq + Dq + d] = den;
    }
}

// ---------------- launch ----------------
extern "C" void kernel_launch(void* const* d_in, const int* in_sizes, int n_in,
                              void* d_out, int out_size)
{
    (void)in_sizes; (void)n_in;
    const float* x     = (const float*)d_in[0];
    const float* ln1_g = (const float*)d_in[1];
    const float* ln1_b = (const float*)d_in[2];
    const float* ln2_g = (const float*)d_in[3];
    const float* ln2_b = (const float*)d_in[4];
    const float* Wr    = (const float*)d_in[5];
    const float* Ww    = (const float*)d_in[6];
    const float* Wk    = (const float*)d_in[7];
    const float* Wv    = (const float*)d_in[8];
    const float* Wo    = (const float*)d_in[9];
    const float* td    = (const float*)d_in[10];
    const float* Wkey  = (const float*)d_in[12];
    const float* Wval  = (const float*)d_in[13];
    const float* Wrec  = (const float*)d_in[14];

    __half *xn,*wq,*wo,*wrk,*wval,*rw,*k2;
    float *act,*x1,*r2,*loc;
    cudaGetSymbolAddress((void**)&xn, g_xn);
    cudaGetSymbolAddress((void**)&wq, g_wqkvw);  cudaGetSymbolAddress((void**)&wo, g_wo);
    cudaGetSymbolAddress((void**)&wrk, g_wrk);   cudaGetSymbolAddress((void**)&wval, g_wval);
    cudaGetSymbolAddress((void**)&rw, g_rw);     cudaGetSymbolAddress((void**)&k2, g_k2);
    cudaGetSymbolAddress((void**)&act, g_act);   cudaGetSymbolAddress((void**)&x1, g_x1);
    cudaGetSymbolAddress((void**)&r2, g_r2);     cudaGetSymbolAddress((void**)&loc, g_loc);

    float* xout = (float*)d_out;
    const int write_state = (out_size >= Mq*Dq + Bq*2*Dq) ? 1 : 0;
    float* state = xout + (size_t)Mq*Dq;

    cudaFuncSetAttribute(mma_gemm<3>, cudaFuncAttributeMaxDynamicSharedMemorySize, SMEM_BYTES);
    cudaFuncSetAttribute(mma_gemm<4>, cudaFuncAttributeMaxDynamicSharedMemorySize, SMEM_BYTES);
    cudaFuncSetAttribute(mma_gemm<5>, cudaFuncAttributeMaxDynamicSharedMemorySize, SMEM_BYTES);
    cudaFuncSetAttribute(mma_gemm<6>, cudaFuncAttributeMaxDynamicSharedMemorySize, SMEM_BYTES);

    const int nDD4 = Dq*Dq/4, nFD4 = Fq*Dq/4;

    // [1] ln1
    ln_cvt_kernel<<<Mq, 256>>>(x, ln1_g, ln1_b, (uint2*)xn);

    // [2] all weight converts (fp32 -> fp16) in one launch
    CvtJobs js;
    js.j[0] = { (const float4*)Wr,   (uint2*)(wq + 0*(size_t)Dq*Dq), nDD4 };
    js.j[1] = { (const float4*)Ww,   (uint2*)(wq + 1*(size_t)Dq*Dq), nDD4 };
    js.j[2] = { (const float4*)Wk,   (uint2*)(wq + 2*(size_t)Dq*Dq), nDD4 };
    js.j[3] = { (const float4*)Wv,   (uint2*)(wq + 3*(size_t)Dq*Dq), nDD4 };
    js.j[4] = { (const float4*)Wo,   (uint2*)wo,                     nDD4 };
    js.j[5] = { (const float4*)Wrec, (uint2*)wrk,                    nDD4 };
    js.j[6] = { (const float4*)Wkey, (uint2*)(wrk + (size_t)Dq*Dq),  nFD4 };
    js.j[7] = { (const float4*)Wval, (uint2*)wval,                   nFD4 };
    cvtall_kernel<<<dim3(nFD4/256, 8), 256>>>(js);

    // [3] fused r|w|k|v GEMM -> act [M,4096]
    mma_gemm<5><<<dim3(32, 64), 256, SMEM_BYTES>>>(xn, wq,
        act, nullptr, nullptr, nullptr, 4096, Dq);
    // [4][5] scan
    scan_p1<<<(CH*Bq*Dq)/256, 256>>>(act, td, loc);
    scan_p3<<<(CH*Bq*Dq)/256, 256>>>(act, td, loc, rw, state, write_state);
    // [6] Wo GEMM: x1 = x + (r*wkv)@Wo^T
    mma_gemm<3><<<dim3(8, 64), 256, SMEM_BYTES>>>(rw, wo,
        x1, nullptr, x, nullptr, 1024, Dq);
    // [7] ln2
    ln_cvt_kernel<<<Mq, 256>>>(x1, ln2_g, ln2_b, (uint2*)xn);
    // [8] fused rec|key GEMM: r2 [M,1024] + k2 fp16 [M,4096]
    mma_gemm<6><<<dim3(40, 64), 256, SMEM_BYTES>>>(xn, wrk,
        r2, k2, nullptr, nullptr, 5120, Dq);
    // [9] Wval GEMM: out = x1 + r2*(k2@Wval^T)
    mma_gemm<4><<<dim3(8, 64), 256, SMEM_BYTES>>>(k2, wval,
        xout, nullptr, x1, r2, 1024, Fq);
}

// round 8
// speedup vs baseline: 6.9648x; 1.0920x over previous
#include <cuda_runtime.h>
#include <cuda_fp16.h>
#include <cstdint>
#include <math.h>

#define Bq 4
#define Sq 2048
#define Dq 1024
#define Fq 4096
#define Mq (Bq*Sq)     // 8192
#define CH 32
#define CL (Sq/CH)     // 64
#define LDT 40         // smem row stride in halves (BK=32 + 8 pad)
#define STAGE_H (128*LDT)            // halves per tile (5120)
#define TILES_PER_STAGE 2            // A, B
#define STG_BYTES (TILES_PER_STAGE*STAGE_H*2)   // 20480
#define NSTAGE 4
#define SMEM_BYTES (NSTAGE*STG_BYTES)           // 81920

// ---------------- scratch ----------------
__device__ __half g_xn[(size_t)Mq*Dq];
__device__ __half g_wqkvw[(size_t)4*Dq*Dq];   // [r rows | v rows | w/k interleaved]
__device__ __half g_wo[(size_t)Dq*Dq];
__device__ __half g_wrk[(size_t)(Dq+Fq)*Dq];  // [rec|key]
__device__ __half g_wval[(size_t)Dq*Fq];
__device__ __half g_r16[(size_t)Mq*Dq];
__device__ __half g_v16[(size_t)Mq*Dq];
__device__ float  g_e  [(size_t)Mq*Dq];       // exp(k - exp(w)), fp32
__device__ float  g_x1 [(size_t)Mq*Dq];
__device__ float  g_r2 [(size_t)Mq*Dq];
__device__ __half g_rw[(size_t)Mq*Dq];
__device__ __half g_k2[(size_t)Mq*Fq];
__device__ float  g_loc[(size_t)CH*Bq*2*Dq];

// ---------------- helpers ----------------
__device__ __forceinline__ uint32_t packh(__half a, __half b) {
    __half2 p(a, b);
    return *reinterpret_cast<uint32_t*>(&p);
}
__device__ __forceinline__ uint2 cvt4(float4 v) {
    return make_uint2(packh(__float2half(v.x), __float2half(v.y)),
                      packh(__float2half(v.z), __float2half(v.w)));
}
__device__ __forceinline__ __half hsig(float x) {
    return __float2half(1.f / (1.f + expf(-x)));
}
__device__ __forceinline__ void ldsm4(uint32_t& r0, uint32_t& r1, uint32_t& r2, uint32_t& r3,
                                      uint32_t addr) {
    asm volatile("ldmatrix.sync.aligned.m8n8.x4.shared.b16 {%0,%1,%2,%3}, [%4];"
                 : "=r"(r0), "=r"(r1), "=r"(r2), "=r"(r3) : "r"(addr));
}

// ---------------- fused weight convert (with optional row interleave) ----------
struct CvtJob  { const float4* s; uint2* d; int n4; int kq; int rstride; };
struct CvtJobs { CvtJob j[8]; };
__global__ void cvtall_kernel(CvtJobs js)
{
    const CvtJob jb = js.j[blockIdx.y];
    const int i = blockIdx.x * blockDim.x + threadIdx.x;
    if (i >= jb.n4) return;
    const int row = i / jb.kq;
    const int col = i - row * jb.kq;
    jb.d[(size_t)row * jb.rstride * jb.kq + col] = cvt4(jb.s[i]);
}

// ---------------- layernorm -> fp16 ----------------
__global__ void ln_cvt_kernel(const float* __restrict__ x,
                              const float* __restrict__ gamma,
                              const float* __restrict__ beta,
                              uint2* __restrict__ oh)
{
    const int row = blockIdx.x;
    const float4* xr = reinterpret_cast<const float4*>(x) + (size_t)row * (Dq/4);
    float4 v = xr[threadIdx.x];
    float s  = v.x + v.y + v.z + v.w;
    float ss = v.x*v.x + v.y*v.y + v.z*v.z + v.w*v.w;
    #pragma unroll
    for (int o = 16; o > 0; o >>= 1) {
        s  += __shfl_xor_sync(0xffffffffu, s,  o);
        ss += __shfl_xor_sync(0xffffffffu, ss, o);
    }
    __shared__ float rs[8], rss[8];
    const int warp = threadIdx.x >> 5;
    if ((threadIdx.x & 31) == 0) { rs[warp] = s; rss[warp] = ss; }
    __syncthreads();
    float ts = 0.f, tss = 0.f;
    #pragma unroll
    for (int i = 0; i < 8; i++) { ts += rs[i]; tss += rss[i]; }
    const float mu   = ts * (1.0f/Dq);
    const float var  = tss * (1.0f/Dq) - mu*mu;
    const float rstd = rsqrtf(var + 1e-5f);
    const float4 g4 = reinterpret_cast<const float4*>(gamma)[threadIdx.x];
    const float4 b4 = reinterpret_cast<const float4*>(beta )[threadIdx.x];
    float4 o;
    o.x = (v.x - mu)*rstd*g4.x + b4.x;
    o.y = (v.y - mu)*rstd*g4.y + b4.y;
    o.z = (v.z - mu)*rstd*g4.z + b4.z;
    o.w = (v.w - mu)*rstd*g4.w + b4.w;
    oh[(size_t)row * (Dq/4) + threadIdx.x] = cvt4(o);
}

// ---------------- HMMA GEMM with ldmatrix fragment loads ----------------------
// C[M,N] = f( A[M,K] @ B[N,K]^T ), fp16 in / fp32 acc, 4-stage cp.async, BK=32.
// EPI: 3 = acc + R -> C;  4 = R + MUL*acc -> C
//      5 = qkvw: x<8 sigmoid->Ch fp16; 8<=x<16 raw->Cv fp16; x>=16 (w,k) pairs ->
//          Ce = expf(k - expf(w)) fp32 at col (col-2048)/2
//      6 = rec|key: x<8 sigmoid->C fp32 [M,1024]; else relu^2 -> Ch fp16 [M,4096]
template<int EPI>
__global__ void __launch_bounds__(256)
mma_gemm(const __half* __restrict__ A, const __half* __restrict__ B,
         float* __restrict__ C, __half* __restrict__ Ch,
         __half* __restrict__ Cv, float* __restrict__ Ce,
         const float* __restrict__ R, const float* __restrict__ MUL,
         int N, int K)
{
    extern __shared__ __half dyn[];

    const int tid = threadIdx.x;
    const int block_row = blockIdx.y * 128;
    const int block_col = blockIdx.x * 128;

    const uint32_t sbase = (uint32_t)__cvta_generic_to_shared(dyn);

    // loaders: 2 threads per row, each 2 x 16B per tile
    const int lr = tid >> 1;
    const int sg = (tid & 1) * 2;
    const __half* gA = A + (size_t)(block_row + lr) * K;
    const __half* gB = B + (size_t)(block_col + lr) * K;
    const uint32_t srow = sbase + (uint32_t)(lr * LDT) * 2;

    #define LOADSTAGE(st, ko)                                                          \
    do {                                                                               \
        const uint32_t sb = srow + (uint32_t)(st) * STG_BYTES;                         \
        _Pragma("unroll")                                                              \
        for (int j = 0; j < 2; j++) {                                                  \
            const int sj = sg + j;                                                     \
            const uint32_t co = (uint32_t)sj * 16;                                     \
            asm volatile("cp.async.cg.shared.global [%0], [%1], 16;" ::                \
                "r"(sb + 0*STAGE_H*2 + co), "l"(gA + (ko) + sj*8));                    \
            asm volatile("cp.async.cg.shared.global [%0], [%1], 16;" ::                \
                "r"(sb + 1*STAGE_H*2 + co), "l"(gB + (ko) + sj*8));                    \
        }                                                                              \
        asm volatile("cp.async.commit_group;" ::: "memory");                           \
    } while (0)

    const int lane = tid & 31;
    const int wm = (tid >> 7);
    const int wn = (tid >> 5) & 3;
    const int grp = lane >> 2, qid = lane & 3;
    const int mb = wm * 64, nb = wn * 32;

    // ldmatrix address components (precompute per-thread row parts)
    const int a_row = (lane & 15);            // row within 16-row tile
    const int a_k8  = (lane >> 4) << 3;       // 0 or 8 (k-offset)
    const int b_row = ((lane >> 4) << 3) + (lane & 7);  // 0..15 over two n-tiles
    const int b_k8  = ((lane >> 3) & 1) << 3; // 0 or 8

    float acc[4][4][4];
    #pragma unroll
    for (int i = 0; i < 4; i++)
        #pragma unroll
        for (int j = 0; j < 4; j++)
            #pragma unroll
            for (int q = 0; q < 4; q++) acc[i][j][q] = 0.f;

    const int KT = K >> 5;
    LOADSTAGE(0, 0);
    LOADSTAGE(1, 32);
    LOADSTAGE(2, 64);

    for (int kt = 0; kt < KT; kt++) {
        const int st = kt & (NSTAGE - 1);
        asm volatile("cp.async.wait_group 2;" ::: "memory");
        __syncthreads();
        if (kt + 3 < KT) LOADSTAGE((kt + 3) & (NSTAGE - 1), (kt + 3) * 32);
        else             asm volatile("cp.async.commit_group;" ::: "memory");

        const uint32_t sA = sbase + (uint32_t)st * STG_BYTES;
        const uint32_t sB = sA + STAGE_H * 2;

        #pragma unroll
        for (int ks = 0; ks < 32; ks += 16) {
            uint32_t ar[4][4], br[4][2];
            #pragma unroll
            for (int mt = 0; mt < 4; mt++) {
                const uint32_t addr = sA +
                    (uint32_t)(((mb + mt*16 + a_row) * LDT + ks + a_k8) << 1);
                ldsm4(ar[mt][0], ar[mt][1], ar[mt][2], ar[mt][3], addr);
            }
            #pragma unroll
            for (int ntp = 0; ntp < 4; ntp += 2) {
                const uint32_t addr = sB +
                    (uint32_t)(((nb + ntp*8 + b_row) * LDT + ks + b_k8) << 1);
                ldsm4(br[ntp][0], br[ntp][1], br[ntp+1][0], br[ntp+1][1], addr);
            }
            #pragma unroll
            for (int mt = 0; mt < 4; mt++)
                #pragma unroll
                for (int nt = 0; nt < 4; nt++) {
                    float* c = acc[mt][nt];
                    asm volatile(
                        "mma.sync.aligned.m16n8k16.row.col.f32.f16.f16.f32 "
                        "{%0,%1,%2,%3}, {%4,%5,%6,%7}, {%8,%9}, {%0,%1,%2,%3};\n"
                        : "+f"(c[0]), "+f"(c[1]), "+f"(c[2]), "+f"(c[3])
                        : "r"(ar[mt][0]), "r"(ar[mt][1]), "r"(ar[mt][2]), "r"(ar[mt][3]),
                          "r"(br[nt][0]), "r"(br[nt][1]));
                }
        }
        __syncthreads();
    }

    // ---------------- epilogue ----------------
    #pragma unroll
    for (int mt = 0; mt < 4; mt++) {
        const size_t r0 = (size_t)block_row + mb + mt*16 + grp;
        const size_t r1 = r0 + 8;
        #pragma unroll
        for (int nt = 0; nt < 4; nt++) {
            const int col = block_col + nb + nt*8 + 2*qid;
            const float* c = acc[mt][nt];
            if constexpr (EPI == 5) {
                if (blockIdx.x < 8) {            // r -> sigmoid fp16
                    const size_t i0 = r0 * 1024 + col;
                    const size_t i1 = r1 * 1024 + col;
                    *reinterpret_cast<uint32_t*>(&Ch[i0]) = packh(hsig(c[0]), hsig(c[1]));
                    *reinterpret_cast<uint32_t*>(&Ch[i1]) = packh(hsig(c[2]), hsig(c[3]));
                } else if (blockIdx.x < 16) {    // v -> fp16 raw
                    const size_t i0 = r0 * 1024 + (col - 1024);
                    const size_t i1 = r1 * 1024 + (col - 1024);
                    *reinterpret_cast<uint32_t*>(&Cv[i0]) =
                        packh(__float2half(c[0]), __float2half(c[1]));
                    *reinterpret_cast<uint32_t*>(&Cv[i1]) =
                        packh(__float2half(c[2]), __float2half(c[3]));
                } else {                         // (w,k) pair -> e fp32
                    const int d = (col - 2048) >> 1;
                    Ce[r0 * 1024 + d] = expf(c[1] - expf(c[0]));
                    Ce[r1 * 1024 + d] = expf(c[3] - expf(c[2]));
                }
            } else if constexpr (EPI == 6) {
                if (blockIdx.x < 8) {
                    const size_t i0 = r0 * 1024 + col;
                    const size_t i1 = r1 * 1024 + col;
                    *reinterpret_cast<float2*>(C + i0) =
                        make_float2(1.f/(1.f+expf(-c[0])), 1.f/(1.f+expf(-c[1])));
                    *reinterpret_cast<float2*>(C + i1) =
                        make_float2(1.f/(1.f+expf(-c[2])), 1.f/(1.f+expf(-c[3])));
                } else {
                    const size_t i0 = r0 * 4096 + (col - 1024);
                    const size_t i1 = r1 * 4096 + (col - 1024);
                    float t0 = fmaxf(c[0],0.f), t1 = fmaxf(c[1],0.f);
                    float t2 = fmaxf(c[2],0.f), t3 = fmaxf(c[3],0.f);
                    *reinterpret_cast<uint32_t*>(&Ch[i0]) =
                        packh(__float2half(t0*t0), __float2half(t1*t1));
                    *reinterpret_cast<uint32_t*>(&Ch[i1]) =
                        packh(__float2half(t2*t2), __float2half(t3*t3));
                }
            } else {
                const size_t i0 = r0 * (size_t)N + col;
                const size_t i1 = r1 * (size_t)N + col;
                float2 o0, o1;
                if constexpr (EPI == 3) {
                    const float2 rr0 = *reinterpret_cast<const float2*>(R + i0);
                    const float2 rr1 = *reinterpret_cast<const float2*>(R + i1);
                    o0 = make_float2(c[0] + rr0.x, c[1] + rr0.y);
                    o1 = make_float2(c[2] + rr1.x, c[3] + rr1.y);
                } else { // EPI 4
                    const float2 rr0 = *reinterpret_cast<const float2*>(R + i0);
                    const float2 rr1 = *reinterpret_cast<const float2*>(R + i1);
                    const float2 mm0 = *reinterpret_cast<const float2*>(MUL + i0);
                    const float2 mm1 = *reinterpret_cast<const float2*>(MUL + i1);
                    o0 = make_float2(rr0.x + mm0.x*c[0], rr0.y + mm0.y*c[1]);
                    o1 = make_float2(rr1.x + mm1.x*c[2], rr1.y + mm1.y*c[3]);
                }
                *reinterpret_cast<float2*>(C + i0) = o0;
                *reinterpret_cast<float2*>(C + i1) = o1;
            }
        }
    }
    #undef LOADSTAGE
}

// ---------------- chunked WKV scan over precomputed e, v ----------------------
__global__ void scan_p1(const float* __restrict__ e, const __half* __restrict__ v,
                        const float* __restrict__ td, float* __restrict__ loc)
{
    const int idx = blockIdx.x * blockDim.x + threadIdx.x;
    const int c  = idx >> 12;
    const int bd = idx & 4095;
    const int b  = bd >> 10;
    const int d  = bd & 1023;
    const float decay = expf(td[d]);
    float num = 0.f, den = 0.f;
    const size_t base = ((size_t)(b * Sq + c * CL)) * 1024 + d;
    #pragma unroll 4
    for (int s = 0; s < CL; s++) {
        const size_t off = base + (size_t)s * 1024;
        const float ev = e[off];
        num = fmaf(decay, num, ev * __half2float(v[off]));
        den = fmaf(decay, den, ev);
    }
    const size_t ci = ((size_t)c * Bq + b) * 2 * Dq + d;
    loc[ci]      = num;
    loc[ci + Dq] = den;
}

__global__ void scan_p3(const __half* __restrict__ r, const float* __restrict__ e,
                        const __half* __restrict__ v, const float* __restrict__ td,
                        const float* __restrict__ loc, __half* __restrict__ rw,
                        float* __restrict__ state, int write_state)
{
    const int idx = blockIdx.x * blockDim.x + threadIdx.x;
    const int c  = idx >> 12;
    const int bd = idx & 4095;
    const int b  = bd >> 10;
    const int d  = bd & 1023;
    const float decay = expf(td[d]);
    const float dl    = expf(td[d] * (float)CL);
    float num = 0.f, den = 0.f;
    for (int cc = 0; cc < c; cc++) {
        const size_t ci = ((size_t)cc * Bq + b) * 2 * Dq + d;
        num = dl * num + loc[ci];
        den = dl * den + loc[ci + Dq];
    }
    const size_t base = ((size_t)(b * Sq + c * CL)) * 1024 + d;
    #pragma unroll 4
    for (int s = 0; s < CL; s++) {
        const size_t off = base + (size_t)s * 1024;
        const float ev = e[off];
        num = fmaf(decay, num, ev * __half2float(v[off]));
        den = fmaf(decay, den, ev);
        rw[off] = __float2half(__half2float(r[off]) * (num / (den + 1e-8f)));
    }
    if (write_state && c == CH - 1) {
        state[(size_t)b*2*Dq + d]      = num;
        state[(size_t)b*2*Dq + Dq + d] = den;
    }
}

// ---------------- launch ----------------
extern "C" void kernel_launch(void* const* d_in, const int* in_sizes, int n_in,
                              void* d_out, int out_size)
{
    (void)in_sizes; (void)n_in;
    const float* x     = (const float*)d_in[0];
    const float* ln1_g = (const float*)d_in[1];
    const float* ln1_b = (const float*)d_in[2];
    const float* ln2_g = (const float*)d_in[3];
    const float* ln2_b = (const float*)d_in[4];
    const float* Wr    = (const float*)d_in[5];
    const float* Ww    = (const float*)d_in[6];
    const float* Wk    = (const float*)d_in[7];
    const float* Wv    = (const float*)d_in[8];
    const float* Wo    = (const float*)d_in[9];
    const float* td    = (const float*)d_in[10];
    const float* Wkey  = (const float*)d_in[12];
    const float* Wval  = (const float*)d_in[13];
    const float* Wrec  = (const float*)d_in[14];

    __half *xn,*wq,*wo,*wrk,*wval,*r16,*v16,*rw,*k2;
    float *eb,*x1,*r2,*loc;
    cudaGetSymbolAddress((void**)&xn, g_xn);
    cudaGetSymbolAddress((void**)&wq, g_wqkvw);  cudaGetSymbolAddress((void**)&wo, g_wo);
    cudaGetSymbolAddress((void**)&wrk, g_wrk);   cudaGetSymbolAddress((void**)&wval, g_wval);
    cudaGetSymbolAddress((void**)&r16, g_r16);   cudaGetSymbolAddress((void**)&v16, g_v16);
    cudaGetSymbolAddress((void**)&eb, g_e);
    cudaGetSymbolAddress((void**)&rw, g_rw);     cudaGetSymbolAddress((void**)&k2, g_k2);
    cudaGetSymbolAddress((void**)&x1, g_x1);
    cudaGetSymbolAddress((void**)&r2, g_r2);     cudaGetSymbolAddress((void**)&loc, g_loc);

    float* xout = (float*)d_out;
    const int write_state = (out_size >= Mq*Dq + Bq*2*Dq) ? 1 : 0;
    float* state = xout + (size_t)Mq*Dq;

    cudaFuncSetAttribute(mma_gemm<3>, cudaFuncAttributeMaxDynamicSharedMemorySize, SMEM_BYTES);
    cudaFuncSetAttribute(mma_gemm<4>, cudaFuncAttributeMaxDynamicSharedMemorySize, SMEM_BYTES);
    cudaFuncSetAttribute(mma_gemm<5>, cudaFuncAttributeMaxDynamicSharedMemorySize, SMEM_BYTES);
    cudaFuncSetAttribute(mma_gemm<6>, cudaFuncAttributeMaxDynamicSharedMemorySize, SMEM_BYTES);

    const int nDD4 = Dq*Dq/4, nFD4 = Fq*Dq/4;
    const int kqD = Dq/4;           // 256 uint2 per row (K=1024)
    uint2* wq2  = (uint2*)wq;
    uint2* wrk2 = (uint2*)wrk;

    // [1] ln1
    ln_cvt_kernel<<<Mq, 256>>>(x, ln1_g, ln1_b, (uint2*)xn);

    // [2] all weight converts (fp32 -> fp16), Ww/Wk row-interleaved into wq[2048:]
    CvtJobs js;
    js.j[0] = { (const float4*)Wr,   wq2,                      nDD4, kqD,   1 };
    js.j[1] = { (const float4*)Wv,   wq2 + (size_t)1024*kqD,   nDD4, kqD,   1 };
    js.j[2] = { (const float4*)Ww,   wq2 + (size_t)2048*kqD,   nDD4, kqD,   2 };
    js.j[3] = { (const float4*)Wk,   wq2 + (size_t)2049*kqD,   nDD4, kqD,   2 };
    js.j[4] = { (const float4*)Wo,   (uint2*)wo,               nDD4, kqD,   1 };
    js.j[5] = { (const float4*)Wrec, wrk2,                     nDD4, kqD,   1 };
    js.j[6] = { (const float4*)Wkey, wrk2 + (size_t)1024*kqD,  nFD4, kqD,   1 };
    js.j[7] = { (const float4*)Wval, (uint2*)wval,             nFD4, Fq/4,  1 };
    cvtall_kernel<<<dim3(nFD4/256, 8), 256>>>(js);

    // [3] fused r|v|wk GEMM -> r16, v16, e
    mma_gemm<5><<<dim3(32, 64), 256, SMEM_BYTES>>>(xn, wq,
        nullptr, r16, v16, eb, nullptr, nullptr, 4096, Dq);
    // [4][5] scan
    scan_p1<<<(CH*Bq*Dq)/256, 256>>>(eb, v16, td, loc);
    scan_p3<<<(CH*Bq*Dq)/256, 256>>>(r16, eb, v16, td, loc, rw, state, write_state);
    // [6] Wo GEMM: x1 = x + (r*wkv)@Wo^T
    mma_gemm<3><<<dim3(8, 64), 256, SMEM_BYTES>>>(rw, wo,
        x1, nullptr, nullptr, nullptr, x, nullptr, 1024, Dq);
    // [7] ln2
    ln_cvt_kernel<<<Mq, 256>>>(x1, ln2_g, ln2_b, (uint2*)xn);
    // [8] fused rec|key GEMM: r2 fp32 [M,1024] + k2 fp16 [M,4096]
    mma_gemm<6><<<dim3(40, 64), 256, SMEM_BYTES>>>(xn, wrk,
        r2, k2, nullptr, nullptr, nullptr, nullptr, 5120, Dq);
    // [9] Wval GEMM: out = x1 + r2*(k2@Wval^T)
    mma_gemm<4><<<dim3(8, 64), 256, SMEM_BYTES>>>(k2, wval,
        xout, nullptr, nullptr, nullptr, x1, r2, 1024, Fq);
}